// round 3
// baseline (speedup 1.0000x reference)
#include <cuda_runtime.h>
#include <math.h>
#include <cstdint>

#define B_ 8
#define N_ 1024
#define HID_ 1024
#define HEADS_ 16
#define HD_ 64
#define GDIM_ 128

// Scratch (allocation-free rule: __device__ globals)
__device__ float g_Q[B_ * N_ * HID_];
__device__ float g_K[B_ * N_ * HID_];
__device__ float g_V[B_ * N_ * HID_];
__device__ float g_O[B_ * N_ * HID_];
__device__ float g_addk[B_ * HID_];

__device__ __forceinline__ uint32_t smem_to_u32(const void* p) {
    uint32_t a;
    asm("{ .reg .u64 t; cvta.to.shared.u64 t, %1; cvt.u32.u64 %0, t; }"
        : "=r"(a) : "l"(p));
    return a;
}
__device__ __forceinline__ uint32_t f2tf32(float f) {
    uint32_t u;
    asm("cvt.rna.tf32.f32 %0, %1;" : "=r"(u) : "f"(f));
    return u;
}
__device__ __forceinline__ void mma_tf32(float c[4], const uint32_t a[4],
                                         const uint32_t b[2]) {
    asm volatile(
        "mma.sync.aligned.m16n8k8.row.col.f32.tf32.tf32.f32 "
        "{%0,%1,%2,%3}, {%4,%5,%6,%7}, {%8,%9}, {%0,%1,%2,%3};"
        : "+f"(c[0]), "+f"(c[1]), "+f"(c[2]), "+f"(c[3])
        : "r"(a[0]), "r"(a[1]), "r"(a[2]), "r"(a[3]), "r"(b[0]), "r"(b[1]));
}
#define STS32(addr, v) \
    asm volatile("st.shared.b32 [%0], %1;" :: "r"(addr), "r"(v) : "memory")
#define LDS128(addr, r0, r1, r2, r3) \
    asm volatile("ld.shared.v4.b32 {%0,%1,%2,%3}, [%4];" \
        : "=r"(r0), "=r"(r1), "=r"(r2), "=r"(r3) : "r"(addr))
#define LDS64(addr, r0, r1) \
    asm volatile("ld.shared.v2.b32 {%0,%1}, [%2];" \
        : "=r"(r0), "=r"(r1) : "r"(addr))

// ===========================================================================
// Prep: addk[b][c] = elu(gc[b] @ Wgk + bgk)[c] + ct_key_emb[ct[b]][c]
// ===========================================================================
__global__ void prep_addk_kernel(const int* __restrict__ ct,
                                 const float* __restrict__ gc,
                                 const float* __restrict__ Wgk,
                                 const float* __restrict__ bgk,
                                 const float* __restrict__ ct_key_emb) {
    int b = blockIdx.x;
    int tid = threadIdx.x;
    __shared__ float g[GDIM_];
    g[tid] = gc[b * GDIM_ + tid];
    __syncthreads();
    int ctb = ct[b];
    for (int c = tid; c < HID_; c += GDIM_) {
        float s = bgk[c];
        #pragma unroll 8
        for (int i = 0; i < GDIM_; i++) s = fmaf(g[i], Wgk[i * HID_ + c], s);
        float e = (s > 0.f) ? s : (expf(s) - 1.f);
        g_addk[b * HID_ + c] = e + ct_key_emb[ctb * HID_ + c];
    }
}

// ===========================================================================
// tf32 mma.sync GEMM: C[8192,1024] = A @ W + bias (+addk per batch)
// CTA 128x128, BK=32, double-buffered smem in FRAGMENT-PERMUTED layout.
// 8 warps: wm = w>>2 (2), wn = w&3 (4); warp tile 64x32 = 4x4 m16n8k8.
// ===========================================================================
// smem: A frags [2][4096]f at 0, B frags [2][4096]f at 32KB. Total 64KB.
#define GEMM_SMEM 65536

__global__ __launch_bounds__(256) void gemm_mma_kernel(
    const float* __restrict__ A, const float* __restrict__ W,
    const float* __restrict__ bias, const float* __restrict__ addk,
    float* __restrict__ C) {
    extern __shared__ float sm[];
    uint32_t Abase = smem_to_u32(sm);
    uint32_t Bbase = Abase + 32768;

    int tid = threadIdx.x;
    int lane = tid & 31, w = tid >> 5;
    int wm = w >> 2, wn = w & 3;
    int m0 = blockIdx.y * 128, n0 = blockIdx.x * 128;

    float c[4][4][4];
    #pragma unroll
    for (int i = 0; i < 4; i++)
        #pragma unroll
        for (int j = 0; j < 4; j++)
            #pragma unroll
            for (int r = 0; r < 4; r++) c[i][j][r] = 0.f;

    // per-thread LDG slots (fixed across chunks)
    // A: slot = tid + it*256 -> m = slot>>3, kq = slot&7  (float4 granules)
    // B: slot = tid + it*256 -> k = slot>>5, nq = slot&31
    float4 aR[4], bR[4];

    #define LDG_CHUNK(k0)                                                     \
        do {                                                                  \
            _Pragma("unroll")                                                 \
            for (int it = 0; it < 4; it++) {                                  \
                int slot = tid + it * 256;                                    \
                int m = slot >> 3, kq = slot & 7;                             \
                aR[it] = *(const float4*)(A + (size_t)(m0 + m) * 1024 +       \
                                          (k0) + kq * 4);                     \
                int k = slot >> 5, nq = slot & 31;                            \
                bR[it] = *(const float4*)(W + (size_t)((k0) + k) * 1024 +     \
                                          n0 + nq * 4);                       \
            }                                                                 \
        } while (0)

    // Fragment-permuted STS.
    // A element (m,kk): ks=kk>>3, i=m>>4, r=m&15, c=kk&7
    //   lane=((r&7)<<2)|(c&3), reg=(r>>3)|((c>>2)<<1)
    //   idx = ((ks*8+i)*32 + lane)*4 + reg
    // B element (k,n): ks=k>>3, cc=k&7, j=n>>3, g=n&7
    //   lane=(g<<2)|(cc&3), reg=cc>>2
    //   idx = ((ks*16+j)*32 + lane)*2 + reg
    #define STS_CHUNK(buf)                                                    \
        do {                                                                  \
            uint32_t Ab = Abase + (buf) * 16384;                              \
            uint32_t Bb = Bbase + (buf) * 16384;                              \
            _Pragma("unroll")                                                 \
            for (int it = 0; it < 4; it++) {                                  \
                int slot = tid + it * 256;                                    \
                int m = slot >> 3, kq = slot & 7;                             \
                int r = m & 15, ib = m >> 4, ks = kq >> 1;                    \
                uint32_t reg = (uint32_t)((r >> 3) | ((kq & 1) << 1));        \
                uint32_t lane0 = (uint32_t)((r & 7) << 2);                    \
                uint32_t base =                                               \
                    Ab + ((((uint32_t)(ks * 8 + ib)) * 32 + lane0) * 4 + reg) * 4; \
                STS32(base + 0 * 16, f2tf32(aR[it].x));                       \
                STS32(base + 1 * 16, f2tf32(aR[it].y));                       \
                STS32(base + 2 * 16, f2tf32(aR[it].z));                       \
                STS32(base + 3 * 16, f2tf32(aR[it].w));                       \
                int k = slot >> 5, nq = slot & 31;                            \
                int ksb = k >> 3, cc = k & 7, jb = nq >> 1;                   \
                uint32_t regb = (uint32_t)(cc >> 2);                          \
                uint32_t laneb = (uint32_t)((((nq & 1) * 4) << 2) | (cc & 3)); \
                uint32_t baseb =                                              \
                    Bb + ((((uint32_t)(ksb * 16 + jb)) * 32 + laneb) * 2 + regb) * 4; \
                STS32(baseb + 0 * 32, f2tf32(bR[it].x));                      \
                STS32(baseb + 1 * 32, f2tf32(bR[it].y));                      \
                STS32(baseb + 2 * 32, f2tf32(bR[it].z));                      \
                STS32(baseb + 3 * 32, f2tf32(bR[it].w));                      \
            }                                                                 \
        } while (0)

    LDG_CHUNK(0);
    STS_CHUNK(0);
    __syncthreads();

    for (int ch = 0; ch < 32; ch++) {
        int buf = ch & 1;
        if (ch < 31) LDG_CHUNK((ch + 1) * 32);

        uint32_t Ab = Abase + buf * 16384;
        uint32_t Bb = Bbase + buf * 16384;
        #pragma unroll
        for (int ks = 0; ks < 4; ks++) {
            uint32_t af[4][4], bf[4][2];
            #pragma unroll
            for (int i = 0; i < 4; i++)
                LDS128(Ab + (((uint32_t)(ks * 8 + wm * 4 + i) * 32 + lane) << 4),
                       af[i][0], af[i][1], af[i][2], af[i][3]);
            #pragma unroll
            for (int j = 0; j < 4; j++)
                LDS64(Bb + (((uint32_t)(ks * 16 + wn * 4 + j) * 32 + lane) << 3),
                      bf[j][0], bf[j][1]);
            #pragma unroll
            for (int i = 0; i < 4; i++)
                #pragma unroll
                for (int j = 0; j < 4; j++) mma_tf32(c[i][j], af[i], bf[j]);
        }

        if (ch < 31) STS_CHUNK(buf ^ 1);
        __syncthreads();
    }

    // Epilogue: c0/c1 -> (row, col), (row, col+1); c2/c3 -> row+8
    int b = m0 >> 10;
    #pragma unroll
    for (int i = 0; i < 4; i++) {
        int row = m0 + wm * 64 + i * 16 + (lane >> 2);
        #pragma unroll
        for (int j = 0; j < 4; j++) {
            int col = n0 + wn * 32 + j * 8 + (lane & 3) * 2;
            float bb0 = bias[col], bb1 = bias[col + 1];
            if (addk) {
                bb0 += addk[b * HID_ + col];
                bb1 += addk[b * HID_ + col + 1];
            }
            *(float2*)(C + (size_t)row * 1024 + col) =
                make_float2(c[i][j][0] + bb0, c[i][j][1] + bb1);
            *(float2*)(C + (size_t)(row + 8) * 1024 + col) =
                make_float2(c[i][j][2] + bb0, c[i][j][3] + bb1);
        }
    }
}

// ===========================================================================
// Flash attention (fp32 CUDA cores, unchanged from R1)
// ===========================================================================
#define TPAD 68
#define ATTN_SMEM (4 * 64 * TPAD * (int)sizeof(float))

__global__ __launch_bounds__(256) void attn_kernel(
    const float* __restrict__ Q, const float* __restrict__ K,
    const float* __restrict__ V, const unsigned char* __restrict__ mask,
    float* __restrict__ O) {
    extern __shared__ float sm[];
    float* Qs = sm;
    float* Ks = Qs + 64 * TPAD;
    float* Vs = Ks + 64 * TPAD;
    float* Ps = Vs + 64 * TPAD;
    __shared__ unsigned char Ms[64];

    int tid = threadIdx.x;
    int qt = blockIdx.x, h = blockIdx.y, b = blockIdx.z;
    int tx = tid & 15, ty = tid >> 4;

    const float inv_scale = 0.125f;

    const float* Qbase = Q + ((size_t)(b * N_ + qt * 64) * HID_ + h * HD_);
    #pragma unroll
    for (int it = 0; it < 4; it++) {
        int i = tid + it * 256;
        int r = i >> 4, d4 = i & 15;
        float4 q4 = *(const float4*)(Qbase + (size_t)r * HID_ + d4 * 4);
        q4.x *= inv_scale; q4.y *= inv_scale; q4.z *= inv_scale; q4.w *= inv_scale;
        *(float4*)&Qs[r * TPAD + d4 * 4] = q4;
    }

    float m_i[4], l_i[4], o[4][4];
    #pragma unroll
    for (int i = 0; i < 4; i++) {
        m_i[i] = -INFINITY;
        l_i[i] = 0.f;
        #pragma unroll
        for (int j = 0; j < 4; j++) o[i][j] = 0.f;
    }

    for (int kt = 0; kt < 16; kt++) {
        const float* Kbase = K + ((size_t)(b * N_ + kt * 64) * HID_ + h * HD_);
        const float* Vbase = V + ((size_t)(b * N_ + kt * 64) * HID_ + h * HD_);
        __syncthreads();
        #pragma unroll
        for (int it = 0; it < 4; it++) {
            int i = tid + it * 256;
            int r = i >> 4, d4 = i & 15;
            *(float4*)&Ks[r * TPAD + d4 * 4] =
                *(const float4*)(Kbase + (size_t)r * HID_ + d4 * 4);
            *(float4*)&Vs[r * TPAD + d4 * 4] =
                *(const float4*)(Vbase + (size_t)r * HID_ + d4 * 4);
        }
        if (tid < 64) Ms[tid] = mask[b * N_ + kt * 64 + tid];
        __syncthreads();

        float s[4][4];
        #pragma unroll
        for (int i = 0; i < 4; i++)
            #pragma unroll
            for (int j = 0; j < 4; j++) s[i][j] = 0.f;
        #pragma unroll
        for (int d = 0; d < 64; d += 4) {
            float4 q[4], kk[4];
            #pragma unroll
            for (int i = 0; i < 4; i++) q[i] = *(float4*)&Qs[(ty * 4 + i) * TPAD + d];
            #pragma unroll
            for (int j = 0; j < 4; j++) kk[j] = *(float4*)&Ks[(tx * 4 + j) * TPAD + d];
            #pragma unroll
            for (int i = 0; i < 4; i++)
                #pragma unroll
                for (int j = 0; j < 4; j++) {
                    s[i][j] = fmaf(q[i].x, kk[j].x, s[i][j]);
                    s[i][j] = fmaf(q[i].y, kk[j].y, s[i][j]);
                    s[i][j] = fmaf(q[i].z, kk[j].z, s[i][j]);
                    s[i][j] = fmaf(q[i].w, kk[j].w, s[i][j]);
                }
        }
        #pragma unroll
        for (int j = 0; j < 4; j++)
            if (Ms[tx * 4 + j]) {
                #pragma unroll
                for (int i = 0; i < 4; i++) s[i][j] = -INFINITY;
            }

        #pragma unroll
        for (int i = 0; i < 4; i++) {
            float rm = fmaxf(fmaxf(s[i][0], s[i][1]), fmaxf(s[i][2], s[i][3]));
            #pragma unroll
            for (int off = 8; off; off >>= 1)
                rm = fmaxf(rm, __shfl_xor_sync(0xffffffffu, rm, off));
            float nm = fmaxf(m_i[i], rm);
            float alpha = __expf(m_i[i] - nm);
            float ps = 0.f;
            #pragma unroll
            for (int j = 0; j < 4; j++) {
                float p = __expf(s[i][j] - nm);
                s[i][j] = p;
                ps += p;
            }
            #pragma unroll
            for (int off = 8; off; off >>= 1)
                ps += __shfl_xor_sync(0xffffffffu, ps, off);
            l_i[i] = l_i[i] * alpha + ps;
            m_i[i] = nm;
            #pragma unroll
            for (int j = 0; j < 4; j++) o[i][j] *= alpha;
        }
        #pragma unroll
        for (int i = 0; i < 4; i++)
            *(float4*)&Ps[(ty * 4 + i) * TPAD + tx * 4] =
                make_float4(s[i][0], s[i][1], s[i][2], s[i][3]);
        __syncthreads();

        #pragma unroll 4
        for (int cc = 0; cc < 64; cc++) {
            float4 v4 = *(float4*)&Vs[cc * TPAD + tx * 4];
            #pragma unroll
            for (int i = 0; i < 4; i++) {
                float p = Ps[(ty * 4 + i) * TPAD + cc];
                o[i][0] = fmaf(p, v4.x, o[i][0]);
                o[i][1] = fmaf(p, v4.y, o[i][1]);
                o[i][2] = fmaf(p, v4.z, o[i][2]);
                o[i][3] = fmaf(p, v4.w, o[i][3]);
            }
        }
    }

    #pragma unroll
    for (int i = 0; i < 4; i++) {
        float inv_l = 1.f / l_i[i];
        int q = qt * 64 + ty * 4 + i;
        float* orow = O + ((size_t)(b * N_ + q) * HID_ + h * HD_ + tx * 4);
        *(float4*)orow = make_float4(o[i][0] * inv_l, o[i][1] * inv_l,
                                     o[i][2] * inv_l, o[i][3] * inv_l);
    }
}

// ===========================================================================
extern "C" void kernel_launch(void* const* d_in, const int* in_sizes, int n_in,
                              void* d_out, int out_size) {
    const float* x = (const float*)d_in[0];
    const int* ct = (const int*)d_in[1];
    const float* gc = (const float*)d_in[2];
    const unsigned char* mask = (const unsigned char*)d_in[3];
    const float* Wq = (const float*)d_in[4];
    const float* bq = (const float*)d_in[5];
    const float* Wk = (const float*)d_in[6];
    const float* bk = (const float*)d_in[7];
    const float* Wv = (const float*)d_in[8];
    const float* bv = (const float*)d_in[9];
    const float* Wo = (const float*)d_in[10];
    const float* bo = (const float*)d_in[11];
    // d_in[12] ct_bias_emb, d_in[14..17] Wg1/bg1/Wg2/bg2 cancel in softmax
    const float* ct_key = (const float*)d_in[13];
    const float* Wgk = (const float*)d_in[18];
    const float* bgk = (const float*)d_in[19];

    float *Qb, *Kb, *Vb, *Ob, *addk;
    cudaGetSymbolAddress((void**)&Qb, g_Q);
    cudaGetSymbolAddress((void**)&Kb, g_K);
    cudaGetSymbolAddress((void**)&Vb, g_V);
    cudaGetSymbolAddress((void**)&Ob, g_O);
    cudaGetSymbolAddress((void**)&addk, g_addk);

    cudaFuncSetAttribute(gemm_mma_kernel, cudaFuncAttributeMaxDynamicSharedMemorySize,
                         GEMM_SMEM);
    cudaFuncSetAttribute(attn_kernel, cudaFuncAttributeMaxDynamicSharedMemorySize,
                         ATTN_SMEM);

    prep_addk_kernel<<<B_, GDIM_>>>(ct, gc, Wgk, bgk, ct_key);

    dim3 ggrid(HID_ / 128, (B_ * N_) / 128);  // (8, 64)
    gemm_mma_kernel<<<ggrid, 256, GEMM_SMEM>>>(x, Wq, bq, nullptr, Qb);
    gemm_mma_kernel<<<ggrid, 256, GEMM_SMEM>>>(x, Wk, bk, addk, Kb);
    gemm_mma_kernel<<<ggrid, 256, GEMM_SMEM>>>(x, Wv, bv, nullptr, Vb);

    dim3 agrid(N_ / 64, HEADS_, B_);  // (16, 16, 8)
    attn_kernel<<<agrid, 256, ATTN_SMEM>>>(Qb, Kb, Vb, mask, Ob);

    gemm_mma_kernel<<<ggrid, 256, GEMM_SMEM>>>(Ob, Wo, bo, nullptr, (float*)d_out);
}

// round 4
// speedup vs baseline: 1.3433x; 1.3433x over previous
#include <cuda_runtime.h>
#include <math.h>
#include <cstdint>

#define B_ 8
#define N_ 1024
#define HID_ 1024
#define HEADS_ 16
#define HD_ 64
#define GDIM_ 128

// Scratch (allocation-free rule: __device__ globals)
__device__ float g_Q[B_ * N_ * HID_];
__device__ float g_K[B_ * N_ * HID_];
__device__ float g_V[B_ * N_ * HID_];
__device__ float g_O[B_ * N_ * HID_];
__device__ float g_addk[B_ * HID_];

__device__ __forceinline__ uint32_t smem_to_u32(const void* p) {
    uint32_t a;
    asm("{ .reg .u64 t; cvta.to.shared.u64 t, %1; cvt.u32.u64 %0, t; }"
        : "=r"(a) : "l"(p));
    return a;
}
__device__ __forceinline__ uint32_t f2tf32(float f) {
    uint32_t u;
    asm("cvt.rna.tf32.f32 %0, %1;" : "=r"(u) : "f"(f));
    return u;
}
__device__ __forceinline__ void mma_tf32(float c[4], const uint32_t a[4],
                                         const uint32_t b[2]) {
    asm volatile(
        "mma.sync.aligned.m16n8k8.row.col.f32.tf32.tf32.f32 "
        "{%0,%1,%2,%3}, {%4,%5,%6,%7}, {%8,%9}, {%0,%1,%2,%3};"
        : "+f"(c[0]), "+f"(c[1]), "+f"(c[2]), "+f"(c[3])
        : "r"(a[0]), "r"(a[1]), "r"(a[2]), "r"(a[3]), "r"(b[0]), "r"(b[1]));
}
#define STS32(addr, v) \
    asm volatile("st.shared.b32 [%0], %1;" :: "r"(addr), "r"(v) : "memory")
#define LDS128(addr, r0, r1, r2, r3) \
    asm volatile("ld.shared.v4.b32 {%0,%1,%2,%3}, [%4];" \
        : "=r"(r0), "=r"(r1), "=r"(r2), "=r"(r3) : "r"(addr))
#define LDS64(addr, r0, r1) \
    asm volatile("ld.shared.v2.b32 {%0,%1}, [%2];" \
        : "=r"(r0), "=r"(r1) : "r"(addr))

// Rotate float4 left by r (out[p] = in[(p+r)&3]), branch-free per-thread.
__device__ __forceinline__ float4 rot4(float4 v, int r) {
    if (r & 1) { float t = v.x; v.x = v.y; v.y = v.z; v.z = v.w; v.w = t; }
    if (r & 2) { float t = v.x; v.x = v.z; v.z = t; t = v.y; v.y = v.w; v.w = t; }
    return v;
}

// ===========================================================================
// Prep: addk[b][c] = elu(gc[b] @ Wgk + bgk)[c] + ct_key_emb[ct[b]][c]
// ===========================================================================
__global__ void prep_addk_kernel(const int* __restrict__ ct,
                                 const float* __restrict__ gc,
                                 const float* __restrict__ Wgk,
                                 const float* __restrict__ bgk,
                                 const float* __restrict__ ct_key_emb) {
    int b = blockIdx.x;
    int tid = threadIdx.x;
    __shared__ float g[GDIM_];
    g[tid] = gc[b * GDIM_ + tid];
    __syncthreads();
    int ctb = ct[b];
    for (int c = tid; c < HID_; c += GDIM_) {
        float s = bgk[c];
        #pragma unroll 8
        for (int i = 0; i < GDIM_; i++) s = fmaf(g[i], Wgk[i * HID_ + c], s);
        float e = (s > 0.f) ? s : (expf(s) - 1.f);
        g_addk[b * HID_ + c] = e + ct_key_emb[ctb * HID_ + c];
    }
}

// ===========================================================================
// tf32 mma.sync GEMM: C[8192,1024] = A @ W + bias (+addk per batch)
// CTA 128x128, BK=32, double-buffered fragment-permuted smem.
// STS side: bank-aware slot mapping + staggered component order ->
// conflict-free 32-bank stores for both A and B.
// ===========================================================================
#define GEMM_SMEM 65536

__global__ __launch_bounds__(256) void gemm_mma_kernel(
    const float* __restrict__ A, const float* __restrict__ W,
    const float* __restrict__ bias, const float* __restrict__ addk,
    float* __restrict__ C) {
    extern __shared__ float sm[];
    uint32_t Abase = smem_to_u32(sm);
    uint32_t Bbase = Abase + 32768;

    int tid = threadIdx.x;
    int lane = tid & 31, w = tid >> 5;
    int wm = w >> 2, wn = w & 3;
    int m0 = blockIdx.y * 128, n0 = blockIdx.x * 128;
    int lanehi = lane >> 3;  // e-stagger rotation (2 bits)

    // --- A LDG/STS mapping (per it in 0..3) ---
    // m = (lane&1) + 2*it + 8*((lane>>1)&1) + 16*w ; kq = ((lane>>2)&1) + 2*lanehi
    int a_mbase = (lane & 1) + 8 * ((lane >> 1) & 1) + 16 * w;  // + 2*it
    int a_kq = ((lane >> 2) & 1) + 2 * lanehi;
    // STS base (e=0): frag = (kq>>1)*8 + w ; r = m&15 ; reg = (r>>3)|((kq&1)<<1)
    // byte = frag*512 + ((r&7)<<2|e)*16 + reg*4
    // --- B LDG/STS mapping ---
    // k = (lane&7) + 8*(w&3) ; nq = lanehi + 4*((w>>2) + 2*it)
    int b_k = (lane & 7) + 8 * (w & 3);
    int b_nqbase = lanehi + 4 * (w >> 2);  // + 8*it
    // frag = (w&3)*16 + (nq>>1) ; reg = (k&7)>>2
    // byte = frag*256 + (((nq&1)*4+e)*4 + (k&3))*8 + reg*4

    float c[4][4][4];
    #pragma unroll
    for (int i = 0; i < 4; i++)
        #pragma unroll
        for (int j = 0; j < 4; j++)
            #pragma unroll
            for (int r = 0; r < 4; r++) c[i][j][r] = 0.f;

    float4 aR[4], bR[4];

    #define LDG_CHUNK(k0)                                                      \
        do {                                                                   \
            _Pragma("unroll")                                                  \
            for (int it = 0; it < 4; it++) {                                   \
                int m = a_mbase + 2 * it;                                      \
                aR[it] = *(const float4*)(A + (size_t)(m0 + m) * 1024 +        \
                                          (k0) + a_kq * 4);                    \
                int nq = b_nqbase + 8 * it;                                    \
                bR[it] = *(const float4*)(W + (size_t)((k0) + b_k) * 1024 +    \
                                          n0 + nq * 4);                        \
            }                                                                  \
        } while (0)

    #define STS_CHUNK(buf)                                                     \
        do {                                                                   \
            uint32_t Ab = Abase + (buf) * 16384;                               \
            uint32_t Bb = Bbase + (buf) * 16384;                               \
            _Pragma("unroll")                                                  \
            for (int it = 0; it < 4; it++) {                                   \
                int m = a_mbase + 2 * it;                                      \
                int r = m & 15;                                                \
                uint32_t frag = (uint32_t)((a_kq >> 1) * 8 + w);               \
                uint32_t reg = (uint32_t)((r >> 3) | ((a_kq & 1) << 1));       \
                uint32_t base = Ab + frag * 512 + ((uint32_t)(r & 7) << 6) +   \
                                reg * 4;                                       \
                float4 av = rot4(aR[it], lanehi);                              \
                /* component s of av is element e=(s+lanehi)&3 */              \
                uint32_t e0 = (uint32_t)(lanehi & 3);                          \
                STS32(base + (((e0 + 0) & 3) << 4), f2tf32(av.x));             \
                STS32(base + (((e0 + 1) & 3) << 4), f2tf32(av.y));             \
                STS32(base + (((e0 + 2) & 3) << 4), f2tf32(av.z));             \
                STS32(base + (((e0 + 3) & 3) << 4), f2tf32(av.w));             \
                int nq = b_nqbase + 8 * it;                                    \
                uint32_t fragb = (uint32_t)((w & 3) * 16 + (nq >> 1));         \
                uint32_t regb = (uint32_t)((b_k & 7) >> 2);                    \
                uint32_t baseb = Bb + fragb * 256 +                            \
                                 ((uint32_t)(nq & 1) * 4) * 32 +               \
                                 ((uint32_t)(b_k & 3)) * 8 + regb * 4;         \
                float4 bv = rot4(bR[it], lanehi);                              \
                STS32(baseb + (((e0 + 0) & 3) << 5), f2tf32(bv.x));            \
                STS32(baseb + (((e0 + 1) & 3) << 5), f2tf32(bv.y));            \
                STS32(baseb + (((e0 + 2) & 3) << 5), f2tf32(bv.z));            \
                STS32(baseb + (((e0 + 3) & 3) << 5), f2tf32(bv.w));            \
            }                                                                  \
        } while (0)

    LDG_CHUNK(0);
    STS_CHUNK(0);
    __syncthreads();

    for (int ch = 0; ch < 32; ch++) {
        int buf = ch & 1;
        if (ch < 31) LDG_CHUNK((ch + 1) * 32);

        uint32_t Ab = Abase + buf * 16384;
        uint32_t Bb = Bbase + buf * 16384;
        #pragma unroll
        for (int ks = 0; ks < 4; ks++) {
            uint32_t af[4][4], bf[4][2];
            #pragma unroll
            for (int i = 0; i < 4; i++)
                LDS128(Ab + (((uint32_t)(ks * 8 + wm * 4 + i) * 32 + lane) << 4),
                       af[i][0], af[i][1], af[i][2], af[i][3]);
            #pragma unroll
            for (int j = 0; j < 4; j++)
                LDS64(Bb + (((uint32_t)(ks * 16 + wn * 4 + j) * 32 + lane) << 3),
                      bf[j][0], bf[j][1]);
            #pragma unroll
            for (int i = 0; i < 4; i++)
                #pragma unroll
                for (int j = 0; j < 4; j++) mma_tf32(c[i][j], af[i], bf[j]);
        }

        if (ch < 31) STS_CHUNK(buf ^ 1);
        __syncthreads();
    }

    // Epilogue
    int b = m0 >> 10;
    #pragma unroll
    for (int i = 0; i < 4; i++) {
        int row = m0 + wm * 64 + i * 16 + (lane >> 2);
        #pragma unroll
        for (int j = 0; j < 4; j++) {
            int col = n0 + wn * 32 + j * 8 + (lane & 3) * 2;
            float bb0 = bias[col], bb1 = bias[col + 1];
            if (addk) {
                bb0 += addk[b * HID_ + col];
                bb1 += addk[b * HID_ + col + 1];
            }
            *(float2*)(C + (size_t)row * 1024 + col) =
                make_float2(c[i][j][0] + bb0, c[i][j][1] + bb1);
            *(float2*)(C + (size_t)(row + 8) * 1024 + col) =
                make_float2(c[i][j][2] + bb0, c[i][j][3] + bb1);
        }
    }
}

// ===========================================================================
// Flash attention (fp32 CUDA cores, unchanged)
// ===========================================================================
#define TPAD 68
#define ATTN_SMEM (4 * 64 * TPAD * (int)sizeof(float))

__global__ __launch_bounds__(256) void attn_kernel(
    const float* __restrict__ Q, const float* __restrict__ K,
    const float* __restrict__ V, const unsigned char* __restrict__ mask,
    float* __restrict__ O) {
    extern __shared__ float sm[];
    float* Qs = sm;
    float* Ks = Qs + 64 * TPAD;
    float* Vs = Ks + 64 * TPAD;
    float* Ps = Vs + 64 * TPAD;
    __shared__ unsigned char Ms[64];

    int tid = threadIdx.x;
    int qt = blockIdx.x, h = blockIdx.y, b = blockIdx.z;
    int tx = tid & 15, ty = tid >> 4;

    const float inv_scale = 0.125f;

    const float* Qbase = Q + ((size_t)(b * N_ + qt * 64) * HID_ + h * HD_);
    #pragma unroll
    for (int it = 0; it < 4; it++) {
        int i = tid + it * 256;
        int r = i >> 4, d4 = i & 15;
        float4 q4 = *(const float4*)(Qbase + (size_t)r * HID_ + d4 * 4);
        q4.x *= inv_scale; q4.y *= inv_scale; q4.z *= inv_scale; q4.w *= inv_scale;
        *(float4*)&Qs[r * TPAD + d4 * 4] = q4;
    }

    float m_i[4], l_i[4], o[4][4];
    #pragma unroll
    for (int i = 0; i < 4; i++) {
        m_i[i] = -INFINITY;
        l_i[i] = 0.f;
        #pragma unroll
        for (int j = 0; j < 4; j++) o[i][j] = 0.f;
    }

    for (int kt = 0; kt < 16; kt++) {
        const float* Kbase = K + ((size_t)(b * N_ + kt * 64) * HID_ + h * HD_);
        const float* Vbase = V + ((size_t)(b * N_ + kt * 64) * HID_ + h * HD_);
        __syncthreads();
        #pragma unroll
        for (int it = 0; it < 4; it++) {
            int i = tid + it * 256;
            int r = i >> 4, d4 = i & 15;
            *(float4*)&Ks[r * TPAD + d4 * 4] =
                *(const float4*)(Kbase + (size_t)r * HID_ + d4 * 4);
            *(float4*)&Vs[r * TPAD + d4 * 4] =
                *(const float4*)(Vbase + (size_t)r * HID_ + d4 * 4);
        }
        if (tid < 64) Ms[tid] = mask[b * N_ + kt * 64 + tid];
        __syncthreads();

        float s[4][4];
        #pragma unroll
        for (int i = 0; i < 4; i++)
            #pragma unroll
            for (int j = 0; j < 4; j++) s[i][j] = 0.f;
        #pragma unroll
        for (int d = 0; d < 64; d += 4) {
            float4 q[4], kk[4];
            #pragma unroll
            for (int i = 0; i < 4; i++) q[i] = *(float4*)&Qs[(ty * 4 + i) * TPAD + d];
            #pragma unroll
            for (int j = 0; j < 4; j++) kk[j] = *(float4*)&Ks[(tx * 4 + j) * TPAD + d];
            #pragma unroll
            for (int i = 0; i < 4; i++)
                #pragma unroll
                for (int j = 0; j < 4; j++) {
                    s[i][j] = fmaf(q[i].x, kk[j].x, s[i][j]);
                    s[i][j] = fmaf(q[i].y, kk[j].y, s[i][j]);
                    s[i][j] = fmaf(q[i].z, kk[j].z, s[i][j]);
                    s[i][j] = fmaf(q[i].w, kk[j].w, s[i][j]);
                }
        }
        #pragma unroll
        for (int j = 0; j < 4; j++)
            if (Ms[tx * 4 + j]) {
                #pragma unroll
                for (int i = 0; i < 4; i++) s[i][j] = -INFINITY;
            }

        #pragma unroll
        for (int i = 0; i < 4; i++) {
            float rm = fmaxf(fmaxf(s[i][0], s[i][1]), fmaxf(s[i][2], s[i][3]));
            #pragma unroll
            for (int off = 8; off; off >>= 1)
                rm = fmaxf(rm, __shfl_xor_sync(0xffffffffu, rm, off));
            float nm = fmaxf(m_i[i], rm);
            float alpha = __expf(m_i[i] - nm);
            float ps = 0.f;
            #pragma unroll
            for (int j = 0; j < 4; j++) {
                float p = __expf(s[i][j] - nm);
                s[i][j] = p;
                ps += p;
            }
            #pragma unroll
            for (int off = 8; off; off >>= 1)
                ps += __shfl_xor_sync(0xffffffffu, ps, off);
            l_i[i] = l_i[i] * alpha + ps;
            m_i[i] = nm;
            #pragma unroll
            for (int j = 0; j < 4; j++) o[i][j] *= alpha;
        }
        #pragma unroll
        for (int i = 0; i < 4; i++)
            *(float4*)&Ps[(ty * 4 + i) * TPAD + tx * 4] =
                make_float4(s[i][0], s[i][1], s[i][2], s[i][3]);
        __syncthreads();

        #pragma unroll 4
        for (int cc = 0; cc < 64; cc++) {
            float4 v4 = *(float4*)&Vs[cc * TPAD + tx * 4];
            #pragma unroll
            for (int i = 0; i < 4; i++) {
                float p = Ps[(ty * 4 + i) * TPAD + cc];
                o[i][0] = fmaf(p, v4.x, o[i][0]);
                o[i][1] = fmaf(p, v4.y, o[i][1]);
                o[i][2] = fmaf(p, v4.z, o[i][2]);
                o[i][3] = fmaf(p, v4.w, o[i][3]);
            }
        }
    }

    #pragma unroll
    for (int i = 0; i < 4; i++) {
        float inv_l = 1.f / l_i[i];
        int q = qt * 64 + ty * 4 + i;
        float* orow = O + ((size_t)(b * N_ + q) * HID_ + h * HD_ + tx * 4);
        *(float4*)orow = make_float4(o[i][0] * inv_l, o[i][1] * inv_l,
                                     o[i][2] * inv_l, o[i][3] * inv_l);
    }
}

// ===========================================================================
extern "C" void kernel_launch(void* const* d_in, const int* in_sizes, int n_in,
                              void* d_out, int out_size) {
    const float* x = (const float*)d_in[0];
    const int* ct = (const int*)d_in[1];
    const float* gc = (const float*)d_in[2];
    const unsigned char* mask = (const unsigned char*)d_in[3];
    const float* Wq = (const float*)d_in[4];
    const float* bq = (const float*)d_in[5];
    const float* Wk = (const float*)d_in[6];
    const float* bk = (const float*)d_in[7];
    const float* Wv = (const float*)d_in[8];
    const float* bv = (const float*)d_in[9];
    const float* Wo = (const float*)d_in[10];
    const float* bo = (const float*)d_in[11];
    // d_in[12] ct_bias_emb, d_in[14..17] Wg1/bg1/Wg2/bg2 cancel in softmax
    const float* ct_key = (const float*)d_in[13];
    const float* Wgk = (const float*)d_in[18];
    const float* bgk = (const float*)d_in[19];

    float *Qb, *Kb, *Vb, *Ob, *addk;
    cudaGetSymbolAddress((void**)&Qb, g_Q);
    cudaGetSymbolAddress((void**)&Kb, g_K);
    cudaGetSymbolAddress((void**)&Vb, g_V);
    cudaGetSymbolAddress((void**)&Ob, g_O);
    cudaGetSymbolAddress((void**)&addk, g_addk);

    cudaFuncSetAttribute(gemm_mma_kernel, cudaFuncAttributeMaxDynamicSharedMemorySize,
                         GEMM_SMEM);
    cudaFuncSetAttribute(attn_kernel, cudaFuncAttributeMaxDynamicSharedMemorySize,
                         ATTN_SMEM);

    prep_addk_kernel<<<B_, GDIM_>>>(ct, gc, Wgk, bgk, ct_key);

    dim3 ggrid(HID_ / 128, (B_ * N_) / 128);  // (8, 64)
    gemm_mma_kernel<<<ggrid, 256, GEMM_SMEM>>>(x, Wq, bq, nullptr, Qb);
    gemm_mma_kernel<<<ggrid, 256, GEMM_SMEM>>>(x, Wk, bk, addk, Kb);
    gemm_mma_kernel<<<ggrid, 256, GEMM_SMEM>>>(x, Wv, bv, nullptr, Vb);

    dim3 agrid(N_ / 64, HEADS_, B_);  // (16, 16, 8)
    attn_kernel<<<agrid, 256, ATTN_SMEM>>>(Qb, Kb, Vb, mask, Ob);

    gemm_mma_kernel<<<ggrid, 256, GEMM_SMEM>>>(Ob, Wo, bo, nullptr, (float*)d_out);
}

// round 5
// speedup vs baseline: 2.4028x; 1.7887x over previous
#include <cuda_runtime.h>
#include <math.h>
#include <cstdint>

#define B_ 8
#define N_ 1024
#define HID_ 1024
#define HEADS_ 16
#define HD_ 64
#define GDIM_ 128

// Scratch (allocation-free rule: __device__ globals)
__device__ float g_Q[B_ * N_ * HID_];
__device__ float g_K[B_ * N_ * HID_];
__device__ float g_V[B_ * N_ * HID_];
__device__ float g_O[B_ * N_ * HID_];
__device__ float g_addk[B_ * HID_];

__device__ __forceinline__ uint32_t smem_to_u32(const void* p) {
    uint32_t a;
    asm("{ .reg .u64 t; cvta.to.shared.u64 t, %1; cvt.u32.u64 %0, t; }"
        : "=r"(a) : "l"(p));
    return a;
}
__device__ __forceinline__ uint32_t f2tf32(float f) {
    uint32_t u;
    asm("cvt.rna.tf32.f32 %0, %1;" : "=r"(u) : "f"(f));
    return u;
}
__device__ __forceinline__ void mma_tf32(float c[4], const uint32_t a[4],
                                         const uint32_t b[2]) {
    asm volatile(
        "mma.sync.aligned.m16n8k8.row.col.f32.tf32.tf32.f32 "
        "{%0,%1,%2,%3}, {%4,%5,%6,%7}, {%8,%9}, {%0,%1,%2,%3};"
        : "+f"(c[0]), "+f"(c[1]), "+f"(c[2]), "+f"(c[3])
        : "r"(a[0]), "r"(a[1]), "r"(a[2]), "r"(a[3]), "r"(b[0]), "r"(b[1]));
}
#define STS32(addr, v) \
    asm volatile("st.shared.b32 [%0], %1;" :: "r"(addr), "r"(v) : "memory")
#define STS64V(addr, v0, v1) \
    asm volatile("st.shared.v2.b32 [%0], {%1,%2};" :: "r"(addr), "r"(v0), "r"(v1) : "memory")
#define LDS128(addr, r0, r1, r2, r3) \
    asm volatile("ld.shared.v4.b32 {%0,%1,%2,%3}, [%4];" \
        : "=r"(r0), "=r"(r1), "=r"(r2), "=r"(r3) : "r"(addr))
#define LDS64(addr, r0, r1) \
    asm volatile("ld.shared.v2.b32 {%0,%1}, [%2];" \
        : "=r"(r0), "=r"(r1) : "r"(addr))

// Rotate float4 left by r (out[p] = in[(p+r)&3]), branch-free per-thread.
__device__ __forceinline__ float4 rot4(float4 v, int r) {
    if (r & 1) { float t = v.x; v.x = v.y; v.y = v.z; v.z = v.w; v.w = t; }
    if (r & 2) { float t = v.x; v.x = v.z; v.z = t; t = v.y; v.y = v.w; v.w = t; }
    return v;
}

// FFMA-pipe exp (deg-5 exp2 poly, rel err ~2e-6). No MUFU.
__device__ __forceinline__ float fexp(float s) {
    float x = s * 1.4426950408889634f;
    int n = __float2int_rn(x);
    float f = x - (float)n;
    float p = 1.3333558146e-3f;
    p = fmaf(p, f, 9.6181291076e-3f);
    p = fmaf(p, f, 5.5504108664e-2f);
    p = fmaf(p, f, 2.4022650696e-1f);
    p = fmaf(p, f, 6.9314718056e-1f);
    p = fmaf(p, f, 1.0f);
    n = max(-126, min(127, n));
    float sc = __int_as_float((uint32_t)(n + 127) << 23);
    return p * sc;
}

// ===========================================================================
// Prep: addk[b][c] = elu(gc[b] @ Wgk + bgk)[c] + ct_key_emb[ct[b]][c]
// ===========================================================================
__global__ void prep_addk_kernel(const int* __restrict__ ct,
                                 const float* __restrict__ gc,
                                 const float* __restrict__ Wgk,
                                 const float* __restrict__ bgk,
                                 const float* __restrict__ ct_key_emb) {
    int b = blockIdx.x;
    int tid = threadIdx.x;
    __shared__ float g[GDIM_];
    g[tid] = gc[b * GDIM_ + tid];
    __syncthreads();
    int ctb = ct[b];
    for (int c = tid; c < HID_; c += GDIM_) {
        float s = bgk[c];
        #pragma unroll 8
        for (int i = 0; i < GDIM_; i++) s = fmaf(g[i], Wgk[i * HID_ + c], s);
        float e = (s > 0.f) ? s : (expf(s) - 1.f);
        g_addk[b * HID_ + c] = e + ct_key_emb[ctb * HID_ + c];
    }
}

// ===========================================================================
// tf32 mma.sync GEMM (unchanged from R4 — 228us each)
// ===========================================================================
#define GEMM_SMEM 65536

__global__ __launch_bounds__(256) void gemm_mma_kernel(
    const float* __restrict__ A, const float* __restrict__ W,
    const float* __restrict__ bias, const float* __restrict__ addk,
    float* __restrict__ C) {
    extern __shared__ float sm[];
    uint32_t Abase = smem_to_u32(sm);
    uint32_t Bbase = Abase + 32768;

    int tid = threadIdx.x;
    int lane = tid & 31, w = tid >> 5;
    int wm = w >> 2, wn = w & 3;
    int m0 = blockIdx.y * 128, n0 = blockIdx.x * 128;
    int lanehi = lane >> 3;

    int a_mbase = (lane & 1) + 8 * ((lane >> 1) & 1) + 16 * w;
    int a_kq = ((lane >> 2) & 1) + 2 * lanehi;
    int b_k = (lane & 7) + 8 * (w & 3);
    int b_nqbase = lanehi + 4 * (w >> 2);

    float c[4][4][4];
    #pragma unroll
    for (int i = 0; i < 4; i++)
        #pragma unroll
        for (int j = 0; j < 4; j++)
            #pragma unroll
            for (int r = 0; r < 4; r++) c[i][j][r] = 0.f;

    float4 aR[4], bR[4];

    #define LDG_CHUNK(k0)                                                      \
        do {                                                                   \
            _Pragma("unroll")                                                  \
            for (int it = 0; it < 4; it++) {                                   \
                int m = a_mbase + 2 * it;                                      \
                aR[it] = *(const float4*)(A + (size_t)(m0 + m) * 1024 +        \
                                          (k0) + a_kq * 4);                    \
                int nq = b_nqbase + 8 * it;                                    \
                bR[it] = *(const float4*)(W + (size_t)((k0) + b_k) * 1024 +    \
                                          n0 + nq * 4);                        \
            }                                                                  \
        } while (0)

    #define STS_CHUNK(buf)                                                     \
        do {                                                                   \
            uint32_t Ab = Abase + (buf) * 16384;                               \
            uint32_t Bb = Bbase + (buf) * 16384;                               \
            _Pragma("unroll")                                                  \
            for (int it = 0; it < 4; it++) {                                   \
                int m = a_mbase + 2 * it;                                      \
                int r = m & 15;                                                \
                uint32_t frag = (uint32_t)((a_kq >> 1) * 8 + w);               \
                uint32_t reg = (uint32_t)((r >> 3) | ((a_kq & 1) << 1));       \
                uint32_t base = Ab + frag * 512 + ((uint32_t)(r & 7) << 6) +   \
                                reg * 4;                                       \
                float4 av = rot4(aR[it], lanehi);                              \
                uint32_t e0 = (uint32_t)(lanehi & 3);                          \
                STS32(base + (((e0 + 0) & 3) << 4), f2tf32(av.x));             \
                STS32(base + (((e0 + 1) & 3) << 4), f2tf32(av.y));             \
                STS32(base + (((e0 + 2) & 3) << 4), f2tf32(av.z));             \
                STS32(base + (((e0 + 3) & 3) << 4), f2tf32(av.w));             \
                int nq = b_nqbase + 8 * it;                                    \
                uint32_t fragb = (uint32_t)((w & 3) * 16 + (nq >> 1));         \
                uint32_t regb = (uint32_t)((b_k & 7) >> 2);                    \
                uint32_t baseb = Bb + fragb * 256 +                            \
                                 ((uint32_t)(nq & 1) * 4) * 32 +               \
                                 ((uint32_t)(b_k & 3)) * 8 + regb * 4;         \
                float4 bv = rot4(bR[it], lanehi);                              \
                STS32(baseb + (((e0 + 0) & 3) << 5), f2tf32(bv.x));            \
                STS32(baseb + (((e0 + 1) & 3) << 5), f2tf32(bv.y));            \
                STS32(baseb + (((e0 + 2) & 3) << 5), f2tf32(bv.z));            \
                STS32(baseb + (((e0 + 3) & 3) << 5), f2tf32(bv.w));            \
            }                                                                  \
        } while (0)

    LDG_CHUNK(0);
    STS_CHUNK(0);
    __syncthreads();

    for (int ch = 0; ch < 32; ch++) {
        int buf = ch & 1;
        if (ch < 31) LDG_CHUNK((ch + 1) * 32);

        uint32_t Ab = Abase + buf * 16384;
        uint32_t Bb = Bbase + buf * 16384;
        #pragma unroll
        for (int ks = 0; ks < 4; ks++) {
            uint32_t af[4][4], bf[4][2];
            #pragma unroll
            for (int i = 0; i < 4; i++)
                LDS128(Ab + (((uint32_t)(ks * 8 + wm * 4 + i) * 32 + lane) << 4),
                       af[i][0], af[i][1], af[i][2], af[i][3]);
            #pragma unroll
            for (int j = 0; j < 4; j++)
                LDS64(Bb + (((uint32_t)(ks * 16 + wn * 4 + j) * 32 + lane) << 3),
                      bf[j][0], bf[j][1]);
            #pragma unroll
            for (int i = 0; i < 4; i++)
                #pragma unroll
                for (int j = 0; j < 4; j++) mma_tf32(c[i][j], af[i], bf[j]);
        }

        if (ch < 31) STS_CHUNK(buf ^ 1);
        __syncthreads();
    }

    int b = m0 >> 10;
    #pragma unroll
    for (int i = 0; i < 4; i++) {
        int row = m0 + wm * 64 + i * 16 + (lane >> 2);
        #pragma unroll
        for (int j = 0; j < 4; j++) {
            int col = n0 + wn * 32 + j * 8 + (lane & 3) * 2;
            float bb0 = bias[col], bb1 = bias[col + 1];
            if (addk) {
                bb0 += addk[b * HID_ + col];
                bb1 += addk[b * HID_ + col + 1];
            }
            *(float2*)(C + (size_t)row * 1024 + col) =
                make_float2(c[i][j][0] + bb0, c[i][j][1] + bb1);
            *(float2*)(C + (size_t)(row + 8) * 1024 + col) =
                make_float2(c[i][j][2] + bb0, c[i][j][3] + bb1);
        }
    }
}

// ===========================================================================
// Tensor-core flash attention, tf32 mma + FFMA-poly exp, no max subtraction.
// CTA = (qtile 128, head, batch). 8 warps, each owns 16 q-rows.
// kv-tile 64, double-buffered fragment-permuted K/V smem.
// smem: K[2][16KB] @0, V[2][16KB] @32768, P[8 warps][4KB] @65536,
//       Msf[2][64] @98304. Total 98816 B.
// ===========================================================================
#define ATTN_SMEM 98816

__global__ __launch_bounds__(256) void attn_mma_kernel(
    const float* __restrict__ Q, const float* __restrict__ K,
    const float* __restrict__ V, const unsigned char* __restrict__ mask,
    float* __restrict__ O) {
    extern __shared__ float sm[];
    uint32_t base = smem_to_u32(sm);
    uint32_t Kf = base;
    uint32_t Vf = base + 32768;
    uint32_t Pw = base + 65536;
    float* Msf = sm + (65536 + 32768) / 4;

    int tid = threadIdx.x;
    int lane = tid & 31, w = tid >> 5;
    int lanehi = lane >> 3;
    int r = lane >> 2, cl = lane & 3;
    int qt = blockIdx.x, h = blockIdx.y, b = blockIdx.z;

    const float* Qg = Q + ((size_t)(b * N_ + qt * 128) * HID_ + h * HD_);
    const float* Kg = K + ((size_t)b * N_ * HID_ + h * HD_);
    const float* Vg = V + ((size_t)b * N_ * HID_ + h * HD_);

    // --- Q fragments in registers: warp w owns rows 16w..16w+15 ---
    uint32_t qf[8][4];
    #pragma unroll
    for (int ks = 0; ks < 8; ks++)
        #pragma unroll
        for (int reg = 0; reg < 4; reg++) {
            int m = 16 * w + r + 8 * (reg & 1);
            int k = 8 * ks + cl + 4 * (reg >> 1);
            qf[ks][reg] = f2tf32(Qg[(size_t)m * HID_ + k] * 0.125f);
        }

    // K/V LDG slots: row kv = (lane&7) + 8w within tile; quad = lanehi + 4*it
    int kvrow = (lane & 7) + 8 * w;
    float4 kR[4], vR[4];

    #define AT_LDG(t)                                                          \
        do {                                                                   \
            const float* kp = Kg + (size_t)((t) * 64 + kvrow) * HID_;          \
            const float* vp = Vg + (size_t)((t) * 64 + kvrow) * HID_;          \
            _Pragma("unroll")                                                  \
            for (int it = 0; it < 4; it++) {                                   \
                kR[it] = *(const float4*)(kp + (lanehi + 4 * it) * 4);         \
                vR[it] = *(const float4*)(vp + (lanehi + 4 * it) * 4);         \
            }                                                                  \
        } while (0)

    // K frag: B operand k=d, n=kv. frag = (d>>3)*8 + w.
    // V frag: B operand k=kv, n=d. frag = w*8 + (d>>3).
    #define AT_STS(buf, t)                                                     \
        do {                                                                   \
            uint32_t Kb = Kf + (buf) * 16384;                                  \
            uint32_t Vb = Vf + (buf) * 16384;                                  \
            int rotK = lanehi >> 1;                                            \
            _Pragma("unroll")                                                  \
            for (int it = 0; it < 4; it++) {                                   \
                int dq = lanehi + 4 * it;                                      \
                uint32_t fragk = (uint32_t)((dq >> 1) * 8 + w);                \
                uint32_t bk = Kb + fragk * 256 + ((uint32_t)(lane & 7) << 5) + \
                              (uint32_t)(dq & 1) * 4;                          \
                float4 kv4 = rot4(kR[it], rotK);                               \
                STS32(bk + (((rotK + 0) & 3) << 3), f2tf32(kv4.x));            \
                STS32(bk + (((rotK + 1) & 3) << 3), f2tf32(kv4.y));            \
                STS32(bk + (((rotK + 2) & 3) << 3), f2tf32(kv4.z));            \
                STS32(bk + (((rotK + 3) & 3) << 3), f2tf32(kv4.w));            \
                uint32_t fragv = (uint32_t)(w * 8 + (dq >> 1));                \
                uint32_t bv = Vb + fragv * 256 +                               \
                              ((uint32_t)(dq & 1) * 4) * 32 +                  \
                              ((uint32_t)(lane & 3)) * 8 +                     \
                              ((uint32_t)((lane >> 2) & 1)) * 4;               \
                float4 vv4 = rot4(vR[it], lanehi);                             \
                uint32_t e0 = (uint32_t)(lanehi & 3);                          \
                STS32(bv + (((e0 + 0) & 3) << 5), f2tf32(vv4.x));              \
                STS32(bv + (((e0 + 1) & 3) << 5), f2tf32(vv4.y));              \
                STS32(bv + (((e0 + 2) & 3) << 5), f2tf32(vv4.z));              \
                STS32(bv + (((e0 + 3) & 3) << 5), f2tf32(vv4.w));              \
            }                                                                  \
            if (tid < 64)                                                      \
                Msf[(buf) * 64 + tid] =                                        \
                    mask[b * N_ + (t) * 64 + tid] ? 0.f : 1.f;                 \
        } while (0)

    // wait — fragv STS mapping must mirror the GEMM B layout exactly:
    // element (k=kv, n): lane' = ((n&7)<<2)|(kv&3), reg = (kv>>2)&1
    // n = 4*dq + e -> n&7 = 4*(dq&1)+e. Base above encodes (dq&1)*4 in the
    // lane' high part ((dq&1)*4)<<2 = *32... wait: lane'*8 = ((4(dq&1)+e)<<2
    // | (kv&3))*8 = (4(dq&1)+e)*32 + (kv&3)*8. e-term = e*32 = (e<<5). OK.

    float oacc[8][4];
    #pragma unroll
    for (int nf = 0; nf < 8; nf++)
        #pragma unroll
        for (int x = 0; x < 4; x++) oacc[nf][x] = 0.f;
    float sum0 = 0.f, sum1 = 0.f;

    int swz = (r >> 1) & 3;
    uint32_t Pmine = Pw + (uint32_t)w * 4096;
    uint32_t PloadBase =
        Pmine + (uint32_t)((r << 2) | (cl ^ swz)) * 16;

    AT_LDG(0);
    AT_STS(0, 0);
    __syncthreads();

    for (int t = 0; t < 16; t++) {
        int buf = t & 1;
        if (t < 15) AT_LDG(t + 1);

        uint32_t Kb = Kf + buf * 16384;
        uint32_t Vb = Vf + buf * 16384;

        // S = Q K^T (scaled)
        float sacc[8][4];
        #pragma unroll
        for (int nf = 0; nf < 8; nf++)
            #pragma unroll
            for (int x = 0; x < 4; x++) sacc[nf][x] = 0.f;
        #pragma unroll
        for (int ks = 0; ks < 8; ks++) {
            uint32_t bf[8][2];
            #pragma unroll
            for (int nf = 0; nf < 8; nf++)
                LDS64(Kb + (uint32_t)(ks * 8 + nf) * 256 + (uint32_t)lane * 8,
                      bf[nf][0], bf[nf][1]);
            #pragma unroll
            for (int nf = 0; nf < 8; nf++) mma_tf32(sacc[nf], qf[ks], bf[nf]);
        }

        // exp + mask + P store (warp-local)
        const float* Mb = Msf + buf * 64;
        #pragma unroll
        for (int nf = 0; nf < 8; nf++) {
            float mm0 = Mb[nf * 8 + 2 * cl];
            float mm1 = Mb[nf * 8 + 2 * cl + 1];
            float p0 = fexp(sacc[nf][0]) * mm0;
            float p1 = fexp(sacc[nf][1]) * mm1;
            float p2 = fexp(sacc[nf][2]) * mm0;
            float p3 = fexp(sacc[nf][3]) * mm1;
            sum0 += p0 + p1;
            sum1 += p2 + p3;
            uint32_t bp = Pmine + (uint32_t)nf * 512 + ((uint32_t)r << 6) +
                          ((uint32_t)(cl >> 1)) * 8;
            uint32_t a_even = bp + (uint32_t)(((2 * (cl & 1)) ^ swz) << 4);
            uint32_t a_odd = bp + (uint32_t)(((2 * (cl & 1) + 1) ^ swz) << 4);
            STS64V(a_even, f2tf32(p0), f2tf32(p2));
            STS64V(a_odd, f2tf32(p1), f2tf32(p3));
        }
        __syncwarp();

        // O += P V
        #pragma unroll
        for (int ks = 0; ks < 8; ks++) {
            uint32_t af[4];
            LDS128(PloadBase + (uint32_t)ks * 512, af[0], af[1], af[2], af[3]);
            uint32_t vf2[8][2];
            #pragma unroll
            for (int nf = 0; nf < 8; nf++)
                LDS64(Vb + (uint32_t)(ks * 8 + nf) * 256 + (uint32_t)lane * 8,
                      vf2[nf][0], vf2[nf][1]);
            #pragma unroll
            for (int nf = 0; nf < 8; nf++) mma_tf32(oacc[nf], af, vf2[nf]);
        }
        __syncwarp();

        if (t < 15) {
            __syncthreads();
            AT_STS(buf ^ 1, t + 1);
            __syncthreads();
        }
    }

    // reduce row sums across the 4 lanes sharing a row
    sum0 += __shfl_xor_sync(0xffffffffu, sum0, 1);
    sum0 += __shfl_xor_sync(0xffffffffu, sum0, 2);
    sum1 += __shfl_xor_sync(0xffffffffu, sum1, 1);
    sum1 += __shfl_xor_sync(0xffffffffu, sum1, 2);
    float inv0 = 1.f / sum0, inv1 = 1.f / sum1;

    int row0 = b * N_ + qt * 128 + 16 * w + r;
    #pragma unroll
    for (int nf = 0; nf < 8; nf++) {
        int col = h * HD_ + nf * 8 + 2 * cl;
        *(float2*)(O + (size_t)row0 * HID_ + col) =
            make_float2(oacc[nf][0] * inv0, oacc[nf][1] * inv0);
        *(float2*)(O + (size_t)(row0 + 8) * HID_ + col) =
            make_float2(oacc[nf][2] * inv1, oacc[nf][3] * inv1);
    }
}

// ===========================================================================
extern "C" void kernel_launch(void* const* d_in, const int* in_sizes, int n_in,
                              void* d_out, int out_size) {
    const float* x = (const float*)d_in[0];
    const int* ct = (const int*)d_in[1];
    const float* gc = (const float*)d_in[2];
    const unsigned char* mask = (const unsigned char*)d_in[3];
    const float* Wq = (const float*)d_in[4];
    const float* bq = (const float*)d_in[5];
    const float* Wk = (const float*)d_in[6];
    const float* bk = (const float*)d_in[7];
    const float* Wv = (const float*)d_in[8];
    const float* bv = (const float*)d_in[9];
    const float* Wo = (const float*)d_in[10];
    const float* bo = (const float*)d_in[11];
    // d_in[12] ct_bias_emb, d_in[14..17] Wg1/bg1/Wg2/bg2 cancel in softmax
    const float* ct_key = (const float*)d_in[13];
    const float* Wgk = (const float*)d_in[18];
    const float* bgk = (const float*)d_in[19];

    float *Qb, *Kb, *Vb, *Ob, *addk;
    cudaGetSymbolAddress((void**)&Qb, g_Q);
    cudaGetSymbolAddress((void**)&Kb, g_K);
    cudaGetSymbolAddress((void**)&Vb, g_V);
    cudaGetSymbolAddress((void**)&Ob, g_O);
    cudaGetSymbolAddress((void**)&addk, g_addk);

    cudaFuncSetAttribute(gemm_mma_kernel, cudaFuncAttributeMaxDynamicSharedMemorySize,
                         GEMM_SMEM);
    cudaFuncSetAttribute(attn_mma_kernel, cudaFuncAttributeMaxDynamicSharedMemorySize,
                         ATTN_SMEM);

    prep_addk_kernel<<<B_, GDIM_>>>(ct, gc, Wgk, bgk, ct_key);

    dim3 ggrid(HID_ / 128, (B_ * N_) / 128);  // (8, 64)
    gemm_mma_kernel<<<ggrid, 256, GEMM_SMEM>>>(x, Wq, bq, nullptr, Qb);
    gemm_mma_kernel<<<ggrid, 256, GEMM_SMEM>>>(x, Wk, bk, addk, Kb);
    gemm_mma_kernel<<<ggrid, 256, GEMM_SMEM>>>(x, Wv, bv, nullptr, Vb);

    dim3 agrid(N_ / 128, HEADS_, B_);  // (8, 16, 8)
    attn_mma_kernel<<<agrid, 256, ATTN_SMEM>>>(Qb, Kb, Vb, mask, Ob);

    gemm_mma_kernel<<<ggrid, 256, GEMM_SMEM>>>(Ob, Wo, bo, nullptr, (float*)d_out);
}

// round 6
// speedup vs baseline: 2.4229x; 1.0084x over previous
#include <cuda_runtime.h>
#include <math.h>
#include <cstdint>

#define B_ 8
#define N_ 1024
#define HID_ 1024
#define HEADS_ 16
#define HD_ 64
#define GDIM_ 128

// Scratch (allocation-free rule: __device__ globals)
__device__ float g_Q[B_ * N_ * HID_];
__device__ float g_K[B_ * N_ * HID_];
__device__ float g_V[B_ * N_ * HID_];
__device__ float g_O[B_ * N_ * HID_];
__device__ float g_addk[B_ * HID_];

__device__ __forceinline__ uint32_t smem_to_u32(const void* p) {
    uint32_t a;
    asm("{ .reg .u64 t; cvta.to.shared.u64 t, %1; cvt.u32.u64 %0, t; }"
        : "=r"(a) : "l"(p));
    return a;
}
__device__ __forceinline__ uint32_t f2tf32(float f) {
    uint32_t u;
    asm("cvt.rna.tf32.f32 %0, %1;" : "=r"(u) : "f"(f));
    return u;
}
__device__ __forceinline__ void mma_tf32(float c[4], const uint32_t a[4],
                                         const uint32_t b[2]) {
    asm volatile(
        "mma.sync.aligned.m16n8k8.row.col.f32.tf32.tf32.f32 "
        "{%0,%1,%2,%3}, {%4,%5,%6,%7}, {%8,%9}, {%0,%1,%2,%3};"
        : "+f"(c[0]), "+f"(c[1]), "+f"(c[2]), "+f"(c[3])
        : "r"(a[0]), "r"(a[1]), "r"(a[2]), "r"(a[3]), "r"(b[0]), "r"(b[1]));
}
#define STS32(addr, v) \
    asm volatile("st.shared.b32 [%0], %1;" :: "r"(addr), "r"(v) : "memory")
#define STS64V(addr, v0, v1) \
    asm volatile("st.shared.v2.b32 [%0], {%1,%2};" :: "r"(addr), "r"(v0), "r"(v1) : "memory")
#define LDS128(addr, r0, r1, r2, r3) \
    asm volatile("ld.shared.v4.b32 {%0,%1,%2,%3}, [%4];" \
        : "=r"(r0), "=r"(r1), "=r"(r2), "=r"(r3) : "r"(addr))
#define LDS64(addr, r0, r1) \
    asm volatile("ld.shared.v2.b32 {%0,%1}, [%2];" \
        : "=r"(r0), "=r"(r1) : "r"(addr))

// Rotate float4 left by r (out[p] = in[(p+r)&3]), branch-free per-thread.
__device__ __forceinline__ float4 rot4(float4 v, int r) {
    if (r & 1) { float t = v.x; v.x = v.y; v.y = v.z; v.z = v.w; v.w = t; }
    if (r & 2) { float t = v.x; v.x = v.z; v.z = t; t = v.y; v.y = v.w; v.w = t; }
    return v;
}

// FFMA-pipe exp (deg-5 exp2 poly, rel err ~2e-6). No MUFU.
__device__ __forceinline__ float fexp(float s) {
    float x = s * 1.4426950408889634f;
    int n = __float2int_rn(x);
    float f = x - (float)n;
    float p = 1.3333558146e-3f;
    p = fmaf(p, f, 9.6181291076e-3f);
    p = fmaf(p, f, 5.5504108664e-2f);
    p = fmaf(p, f, 2.4022650696e-1f);
    p = fmaf(p, f, 6.9314718056e-1f);
    p = fmaf(p, f, 1.0f);
    n = max(-126, min(127, n));
    float sc = __int_as_float((uint32_t)(n + 127) << 23);
    return p * sc;
}

// ===========================================================================
// Prep: addk[b][c] = elu(gc[b] @ Wgk + bgk)[c] + ct_key_emb[ct[b]][c]
// ===========================================================================
__global__ void prep_addk_kernel(const int* __restrict__ ct,
                                 const float* __restrict__ gc,
                                 const float* __restrict__ Wgk,
                                 const float* __restrict__ bgk,
                                 const float* __restrict__ ct_key_emb) {
    int b = blockIdx.x;
    int tid = threadIdx.x;
    __shared__ float g[GDIM_];
    g[tid] = gc[b * GDIM_ + tid];
    __syncthreads();
    int ctb = ct[b];
    for (int c = tid; c < HID_; c += GDIM_) {
        float s = bgk[c];
        #pragma unroll 8
        for (int i = 0; i < GDIM_; i++) s = fmaf(g[i], Wgk[i * HID_ + c], s);
        float e = (s > 0.f) ? s : (expf(s) - 1.f);
        g_addk[b * HID_ + c] = e + ct_key_emb[ctb * HID_ + c];
    }
}

// ===========================================================================
// tf32 mma.sync GEMM, BK=16, 2 CTAs/SM. blockIdx.z selects {W,bias,C}.
// CTA tile 128x128, 8 warps (wm=w>>2, wn=w&3), warp tile 64x32.
// smem: A[2][8KB] @0, B[2][8KB] @16384. Total 32KB.
// ===========================================================================
#define GEMM_SMEM 32768

__global__ __launch_bounds__(256, 2) void gemm3_mma_kernel(
    const float* __restrict__ A,
    const float* __restrict__ W0, const float* __restrict__ W1,
    const float* __restrict__ W2,
    const float* __restrict__ bi0, const float* __restrict__ bi1,
    const float* __restrict__ bi2,
    const float* __restrict__ addk,
    float* __restrict__ C0, float* __restrict__ C1, float* __restrict__ C2) {
    extern __shared__ float sm[];
    uint32_t Abase = smem_to_u32(sm);
    uint32_t Bbase = Abase + 16384;

    int z = blockIdx.z;
    const float* W = (z == 0) ? W0 : ((z == 1) ? W1 : W2);
    const float* bias = (z == 0) ? bi0 : ((z == 1) ? bi1 : bi2);
    float* C = (z == 0) ? C0 : ((z == 1) ? C1 : C2);
    const float* ak = (z == 1) ? addk : nullptr;

    int tid = threadIdx.x;
    int lane = tid & 31, w = tid >> 5;
    int wm = w >> 2, wn = w & 3;
    int m0 = blockIdx.y * 128, n0 = blockIdx.x * 128;

    int l0 = lane & 1, l1 = (lane >> 1) & 1, l2 = (lane >> 2) & 1;
    int kqA = lane >> 3;                       // 0..3, A quad-column
    int e0A = l2 | (((lane >> 4) & 1) << 1);   // A component stagger
    int a_mbase = w * 16 + l0 + 4 * l2 + 8 * l1;  // + 2*it
    uint32_t a_f = (uint32_t)((kqA >> 1) * 8 + w);
    uint32_t a_reg = (uint32_t)(l1 | ((kqA & 1) << 1));

    int kB = (lane & 7) + 8 * (w & 1);
    int nq_base = (lane >> 3) + 4 * (w >> 1);  // + 16*it
    int e0B = (lane >> 3) & 3;                 // B component stagger

    float c[4][4][4];
    #pragma unroll
    for (int i = 0; i < 4; i++)
        #pragma unroll
        for (int j = 0; j < 4; j++)
            #pragma unroll
            for (int r = 0; r < 4; r++) c[i][j][r] = 0.f;

    float4 aR[2], bR[2];

    #define LDG_CHUNK(k0)                                                      \
        do {                                                                   \
            _Pragma("unroll")                                                  \
            for (int it = 0; it < 2; it++) {                                   \
                int m = a_mbase + 2 * it;                                      \
                aR[it] = *(const float4*)(A + (size_t)(m0 + m) * 1024 +        \
                                          (k0) + kqA * 4);                     \
                int nq = nq_base + 16 * it;                                    \
                bR[it] = *(const float4*)(W + (size_t)((k0) + kB) * 1024 +     \
                                          n0 + nq * 4);                        \
            }                                                                  \
        } while (0)

    #define STS_CHUNK(buf)                                                     \
        do {                                                                   \
            uint32_t Ab = Abase + (buf) * 8192;                                \
            uint32_t Bb = Bbase + (buf) * 8192;                                \
            _Pragma("unroll")                                                  \
            for (int it = 0; it < 2; it++) {                                   \
                int r7 = l0 + 2 * it + 4 * l2;                                 \
                uint32_t base = Ab + a_f * 512 + ((uint32_t)r7 << 6) +         \
                                a_reg * 4;                                     \
                float4 av = rot4(aR[it], e0A);                                 \
                STS32(base + (((e0A + 0) & 3) << 4), f2tf32(av.x));            \
                STS32(base + (((e0A + 1) & 3) << 4), f2tf32(av.y));            \
                STS32(base + (((e0A + 2) & 3) << 4), f2tf32(av.z));            \
                STS32(base + (((e0A + 3) & 3) << 4), f2tf32(av.w));            \
                int nq = nq_base + 16 * it;                                    \
                uint32_t fb = (uint32_t)((w & 1) * 16 + (nq >> 1));            \
                uint32_t baseb = Bb + fb * 256 + (uint32_t)(nq & 1) * 128 +    \
                                 (uint32_t)(kB & 3) * 8 +                      \
                                 (uint32_t)((kB >> 2) & 1) * 4;                \
                float4 bv = rot4(bR[it], e0B);                                 \
                STS32(baseb + (((e0B + 0) & 3) << 5), f2tf32(bv.x));           \
                STS32(baseb + (((e0B + 1) & 3) << 5), f2tf32(bv.y));           \
                STS32(baseb + (((e0B + 2) & 3) << 5), f2tf32(bv.z));           \
                STS32(baseb + (((e0B + 3) & 3) << 5), f2tf32(bv.w));           \
            }                                                                  \
        } while (0)

    LDG_CHUNK(0);
    STS_CHUNK(0);
    __syncthreads();

    for (int ch = 0; ch < 64; ch++) {
        int buf = ch & 1;
        if (ch < 63) LDG_CHUNK((ch + 1) * 16);

        uint32_t Ab = Abase + buf * 8192;
        uint32_t Bb = Bbase + buf * 8192;
        #pragma unroll
        for (int ks = 0; ks < 2; ks++) {
            uint32_t af[4][4], bf[4][2];
            #pragma unroll
            for (int i = 0; i < 4; i++)
                LDS128(Ab + (((uint32_t)(ks * 8 + wm * 4 + i) * 32 + lane) << 4),
                       af[i][0], af[i][1], af[i][2], af[i][3]);
            #pragma unroll
            for (int j = 0; j < 4; j++)
                LDS64(Bb + (((uint32_t)(ks * 16 + wn * 4 + j) * 32 + lane) << 3),
                      bf[j][0], bf[j][1]);
            #pragma unroll
            for (int i = 0; i < 4; i++)
                #pragma unroll
                for (int j = 0; j < 4; j++) mma_tf32(c[i][j], af[i], bf[j]);
        }

        if (ch < 63) STS_CHUNK(buf ^ 1);
        __syncthreads();
    }

    int b = m0 >> 10;
    #pragma unroll
    for (int i = 0; i < 4; i++) {
        int row = m0 + wm * 64 + i * 16 + (lane >> 2);
        #pragma unroll
        for (int j = 0; j < 4; j++) {
            int col = n0 + wn * 32 + j * 8 + (lane & 3) * 2;
            float bb0 = bias[col], bb1 = bias[col + 1];
            if (ak) {
                bb0 += ak[b * HID_ + col];
                bb1 += ak[b * HID_ + col + 1];
            }
            *(float2*)(C + (size_t)row * 1024 + col) =
                make_float2(c[i][j][0] + bb0, c[i][j][1] + bb1);
            *(float2*)(C + (size_t)(row + 8) * 1024 + col) =
                make_float2(c[i][j][2] + bb0, c[i][j][3] + bb1);
        }
    }
}

// ===========================================================================
// Tensor-core flash attention (unchanged from R5)
// ===========================================================================
#define ATTN_SMEM 98816

__global__ __launch_bounds__(256) void attn_mma_kernel(
    const float* __restrict__ Q, const float* __restrict__ K,
    const float* __restrict__ V, const unsigned char* __restrict__ mask,
    float* __restrict__ O) {
    extern __shared__ float sm[];
    uint32_t base = smem_to_u32(sm);
    uint32_t Kf = base;
    uint32_t Vf = base + 32768;
    uint32_t Pw = base + 65536;
    float* Msf = sm + (65536 + 32768) / 4;

    int tid = threadIdx.x;
    int lane = tid & 31, w = tid >> 5;
    int lanehi = lane >> 3;
    int r = lane >> 2, cl = lane & 3;
    int qt = blockIdx.x, h = blockIdx.y, b = blockIdx.z;

    const float* Qg = Q + ((size_t)(b * N_ + qt * 128) * HID_ + h * HD_);
    const float* Kg = K + ((size_t)b * N_ * HID_ + h * HD_);
    const float* Vg = V + ((size_t)b * N_ * HID_ + h * HD_);

    uint32_t qf[8][4];
    #pragma unroll
    for (int ks = 0; ks < 8; ks++)
        #pragma unroll
        for (int reg = 0; reg < 4; reg++) {
            int m = 16 * w + r + 8 * (reg & 1);
            int k = 8 * ks + cl + 4 * (reg >> 1);
            qf[ks][reg] = f2tf32(Qg[(size_t)m * HID_ + k] * 0.125f);
        }

    int kvrow = (lane & 7) + 8 * w;
    float4 kR[4], vR[4];

    #define AT_LDG(t)                                                          \
        do {                                                                   \
            const float* kp = Kg + (size_t)((t) * 64 + kvrow) * HID_;          \
            const float* vp = Vg + (size_t)((t) * 64 + kvrow) * HID_;          \
            _Pragma("unroll")                                                  \
            for (int it = 0; it < 4; it++) {                                   \
                kR[it] = *(const float4*)(kp + (lanehi + 4 * it) * 4);         \
                vR[it] = *(const float4*)(vp + (lanehi + 4 * it) * 4);         \
            }                                                                  \
        } while (0)

    #define AT_STS(buf, t)                                                     \
        do {                                                                   \
            uint32_t Kb = Kf + (buf) * 16384;                                  \
            uint32_t Vb = Vf + (buf) * 16384;                                  \
            int rotK = lanehi >> 1;                                            \
            _Pragma("unroll")                                                  \
            for (int it = 0; it < 4; it++) {                                   \
                int dq = lanehi + 4 * it;                                      \
                uint32_t fragk = (uint32_t)((dq >> 1) * 8 + w);                \
                uint32_t bk = Kb + fragk * 256 + ((uint32_t)(lane & 7) << 5) + \
                              (uint32_t)(dq & 1) * 4;                          \
                float4 kv4 = rot4(kR[it], rotK);                               \
                STS32(bk + (((rotK + 0) & 3) << 3), f2tf32(kv4.x));            \
                STS32(bk + (((rotK + 1) & 3) << 3), f2tf32(kv4.y));            \
                STS32(bk + (((rotK + 2) & 3) << 3), f2tf32(kv4.z));            \
                STS32(bk + (((rotK + 3) & 3) << 3), f2tf32(kv4.w));            \
                uint32_t fragv = (uint32_t)(w * 8 + (dq >> 1));                \
                uint32_t bv = Vb + fragv * 256 +                               \
                              ((uint32_t)(dq & 1) * 4) * 32 +                  \
                              ((uint32_t)(lane & 3)) * 8 +                     \
                              ((uint32_t)((lane >> 2) & 1)) * 4;               \
                float4 vv4 = rot4(vR[it], lanehi);                             \
                uint32_t e0 = (uint32_t)(lanehi & 3);                          \
                STS32(bv + (((e0 + 0) & 3) << 5), f2tf32(vv4.x));              \
                STS32(bv + (((e0 + 1) & 3) << 5), f2tf32(vv4.y));              \
                STS32(bv + (((e0 + 2) & 3) << 5), f2tf32(vv4.z));              \
                STS32(bv + (((e0 + 3) & 3) << 5), f2tf32(vv4.w));              \
            }                                                                  \
            if (tid < 64)                                                      \
                Msf[(buf) * 64 + tid] =                                        \
                    mask[b * N_ + (t) * 64 + tid] ? 0.f : 1.f;                 \
        } while (0)

    float oacc[8][4];
    #pragma unroll
    for (int nf = 0; nf < 8; nf++)
        #pragma unroll
        for (int x = 0; x < 4; x++) oacc[nf][x] = 0.f;
    float sum0 = 0.f, sum1 = 0.f;

    int swz = (r >> 1) & 3;
    uint32_t Pmine = Pw + (uint32_t)w * 4096;
    uint32_t PloadBase = Pmine + (uint32_t)((r << 2) | (cl ^ swz)) * 16;

    AT_LDG(0);
    AT_STS(0, 0);
    __syncthreads();

    for (int t = 0; t < 16; t++) {
        int buf = t & 1;
        if (t < 15) AT_LDG(t + 1);

        uint32_t Kb = Kf + buf * 16384;
        uint32_t Vb = Vf + buf * 16384;

        float sacc[8][4];
        #pragma unroll
        for (int nf = 0; nf < 8; nf++)
            #pragma unroll
            for (int x = 0; x < 4; x++) sacc[nf][x] = 0.f;
        #pragma unroll
        for (int ks = 0; ks < 8; ks++) {
            uint32_t bf[8][2];
            #pragma unroll
            for (int nf = 0; nf < 8; nf++)
                LDS64(Kb + (uint32_t)(ks * 8 + nf) * 256 + (uint32_t)lane * 8,
                      bf[nf][0], bf[nf][1]);
            #pragma unroll
            for (int nf = 0; nf < 8; nf++) mma_tf32(sacc[nf], qf[ks], bf[nf]);
        }

        const float* Mb = Msf + buf * 64;
        #pragma unroll
        for (int nf = 0; nf < 8; nf++) {
            float mm0 = Mb[nf * 8 + 2 * cl];
            float mm1 = Mb[nf * 8 + 2 * cl + 1];
            float p0 = fexp(sacc[nf][0]) * mm0;
            float p1 = fexp(sacc[nf][1]) * mm1;
            float p2 = fexp(sacc[nf][2]) * mm0;
            float p3 = fexp(sacc[nf][3]) * mm1;
            sum0 += p0 + p1;
            sum1 += p2 + p3;
            uint32_t bp = Pmine + (uint32_t)nf * 512 + ((uint32_t)r << 6) +
                          ((uint32_t)(cl >> 1)) * 8;
            uint32_t a_even = bp + (uint32_t)(((2 * (cl & 1)) ^ swz) << 4);
            uint32_t a_odd = bp + (uint32_t)(((2 * (cl & 1) + 1) ^ swz) << 4);
            STS64V(a_even, f2tf32(p0), f2tf32(p2));
            STS64V(a_odd, f2tf32(p1), f2tf32(p3));
        }
        __syncwarp();

        #pragma unroll
        for (int ks = 0; ks < 8; ks++) {
            uint32_t af[4];
            LDS128(PloadBase + (uint32_t)ks * 512, af[0], af[1], af[2], af[3]);
            uint32_t vf2[8][2];
            #pragma unroll
            for (int nf = 0; nf < 8; nf++)
                LDS64(Vb + (uint32_t)(ks * 8 + nf) * 256 + (uint32_t)lane * 8,
                      vf2[nf][0], vf2[nf][1]);
            #pragma unroll
            for (int nf = 0; nf < 8; nf++) mma_tf32(oacc[nf], af, vf2[nf]);
        }
        __syncwarp();

        if (t < 15) {
            __syncthreads();
            AT_STS(buf ^ 1, t + 1);
            __syncthreads();
        }
    }

    sum0 += __shfl_xor_sync(0xffffffffu, sum0, 1);
    sum0 += __shfl_xor_sync(0xffffffffu, sum0, 2);
    sum1 += __shfl_xor_sync(0xffffffffu, sum1, 1);
    sum1 += __shfl_xor_sync(0xffffffffu, sum1, 2);
    float inv0 = 1.f / sum0, inv1 = 1.f / sum1;

    int row0 = b * N_ + qt * 128 + 16 * w + r;
    #pragma unroll
    for (int nf = 0; nf < 8; nf++) {
        int col = h * HD_ + nf * 8 + 2 * cl;
        *(float2*)(O + (size_t)row0 * HID_ + col) =
            make_float2(oacc[nf][0] * inv0, oacc[nf][1] * inv0);
        *(float2*)(O + (size_t)(row0 + 8) * HID_ + col) =
            make_float2(oacc[nf][2] * inv1, oacc[nf][3] * inv1);
    }
}

// ===========================================================================
extern "C" void kernel_launch(void* const* d_in, const int* in_sizes, int n_in,
                              void* d_out, int out_size) {
    const float* x = (const float*)d_in[0];
    const int* ct = (const int*)d_in[1];
    const float* gc = (const float*)d_in[2];
    const unsigned char* mask = (const unsigned char*)d_in[3];
    const float* Wq = (const float*)d_in[4];
    const float* bq = (const float*)d_in[5];
    const float* Wk = (const float*)d_in[6];
    const float* bk = (const float*)d_in[7];
    const float* Wv = (const float*)d_in[8];
    const float* bv = (const float*)d_in[9];
    const float* Wo = (const float*)d_in[10];
    const float* bo = (const float*)d_in[11];
    // d_in[12] ct_bias_emb, d_in[14..17] Wg1/bg1/Wg2/bg2 cancel in softmax
    const float* ct_key = (const float*)d_in[13];
    const float* Wgk = (const float*)d_in[18];
    const float* bgk = (const float*)d_in[19];

    float *Qb, *Kb, *Vb, *Ob, *addk;
    cudaGetSymbolAddress((void**)&Qb, g_Q);
    cudaGetSymbolAddress((void**)&Kb, g_K);
    cudaGetSymbolAddress((void**)&Vb, g_V);
    cudaGetSymbolAddress((void**)&Ob, g_O);
    cudaGetSymbolAddress((void**)&addk, g_addk);

    cudaFuncSetAttribute(gemm3_mma_kernel, cudaFuncAttributeMaxDynamicSharedMemorySize,
                         GEMM_SMEM);
    cudaFuncSetAttribute(attn_mma_kernel, cudaFuncAttributeMaxDynamicSharedMemorySize,
                         ATTN_SMEM);

    prep_addk_kernel<<<B_, GDIM_>>>(ct, gc, Wgk, bgk, ct_key);

    // Fused Q/K/V projections: z selects weight/bias/output; addk applies to K.
    dim3 qkvgrid(HID_ / 128, (B_ * N_) / 128, 3);  // (8, 64, 3)
    gemm3_mma_kernel<<<qkvgrid, 256, GEMM_SMEM>>>(
        x, Wq, Wk, Wv, bq, bk, bv, addk, Qb, Kb, Vb);

    dim3 agrid(N_ / 128, HEADS_, B_);  // (8, 16, 8)
    attn_mma_kernel<<<agrid, 256, ATTN_SMEM>>>(Qb, Kb, Vb, mask, Ob);

    dim3 ogrid(HID_ / 128, (B_ * N_) / 128, 1);
    gemm3_mma_kernel<<<ogrid, 256, GEMM_SMEM>>>(
        Ob, Wo, Wo, Wo, bo, bo, bo, nullptr, (float*)d_out, nullptr, nullptr);
}

// round 7
// speedup vs baseline: 2.4317x; 1.0036x over previous
#include <cuda_runtime.h>
#include <math.h>
#include <cstdint>

#define B_ 8
#define N_ 1024
#define HID_ 1024
#define HEADS_ 16
#define HD_ 64
#define GDIM_ 128

// Scratch (allocation-free rule: __device__ globals)
__device__ float g_Q[B_ * N_ * HID_];
__device__ float g_K[B_ * N_ * HID_];
__device__ float g_V[B_ * N_ * HID_];
__device__ float g_O[B_ * N_ * HID_];
__device__ float g_addk[B_ * HID_];

__device__ __forceinline__ uint32_t smem_to_u32(const void* p) {
    uint32_t a;
    asm("{ .reg .u64 t; cvta.to.shared.u64 t, %1; cvt.u32.u64 %0, t; }"
        : "=r"(a) : "l"(p));
    return a;
}
__device__ __forceinline__ uint32_t f2tf32(float f) {
    uint32_t u;
    asm("cvt.rna.tf32.f32 %0, %1;" : "=r"(u) : "f"(f));
    return u;
}
__device__ __forceinline__ void mma_tf32(float c[4], const uint32_t a[4],
                                         const uint32_t b[2]) {
    asm volatile(
        "mma.sync.aligned.m16n8k8.row.col.f32.tf32.tf32.f32 "
        "{%0,%1,%2,%3}, {%4,%5,%6,%7}, {%8,%9}, {%0,%1,%2,%3};"
        : "+f"(c[0]), "+f"(c[1]), "+f"(c[2]), "+f"(c[3])
        : "r"(a[0]), "r"(a[1]), "r"(a[2]), "r"(a[3]), "r"(b[0]), "r"(b[1]));
}
#define STS32(addr, v) \
    asm volatile("st.shared.b32 [%0], %1;" :: "r"(addr), "r"(v) : "memory")
#define STS64V(addr, v0, v1) \
    asm volatile("st.shared.v2.b32 [%0], {%1,%2};" :: "r"(addr), "r"(v0), "r"(v1) : "memory")
#define LDS128(addr, r0, r1, r2, r3) \
    asm volatile("ld.shared.v4.b32 {%0,%1,%2,%3}, [%4];" \
        : "=r"(r0), "=r"(r1), "=r"(r2), "=r"(r3) : "r"(addr))
#define LDS64(addr, r0, r1) \
    asm volatile("ld.shared.v2.b32 {%0,%1}, [%2];" \
        : "=r"(r0), "=r"(r1) : "r"(addr))

// Rotate float4 left by r (out[p] = in[(p+r)&3]), branch-free per-thread.
__device__ __forceinline__ float4 rot4(float4 v, int r) {
    if (r & 1) { float t = v.x; v.x = v.y; v.y = v.z; v.z = v.w; v.w = t; }
    if (r & 2) { float t = v.x; v.x = v.z; v.z = t; t = v.y; v.y = v.w; v.w = t; }
    return v;
}

// FFMA-pipe exp (deg-5 exp2 poly, rel err ~2e-6). No MUFU.
__device__ __forceinline__ float fexp(float s) {
    float x = s * 1.4426950408889634f;
    int n = __float2int_rn(x);
    float f = x - (float)n;
    float p = 1.3333558146e-3f;
    p = fmaf(p, f, 9.6181291076e-3f);
    p = fmaf(p, f, 5.5504108664e-2f);
    p = fmaf(p, f, 2.4022650696e-1f);
    p = fmaf(p, f, 6.9314718056e-1f);
    p = fmaf(p, f, 1.0f);
    n = max(-126, min(127, n));
    float sc = __int_as_float((uint32_t)(n + 127) << 23);
    return p * sc;
}

// ===========================================================================
// Prep: addk[b][c] = elu(gc[b] @ Wgk + bgk)[c] + ct_key_emb[ct[b]][c]
// ===========================================================================
__global__ void prep_addk_kernel(const int* __restrict__ ct,
                                 const float* __restrict__ gc,
                                 const float* __restrict__ Wgk,
                                 const float* __restrict__ bgk,
                                 const float* __restrict__ ct_key_emb) {
    int b = blockIdx.x;
    int tid = threadIdx.x;
    __shared__ float g[GDIM_];
    g[tid] = gc[b * GDIM_ + tid];
    __syncthreads();
    int ctb = ct[b];
    for (int c = tid; c < HID_; c += GDIM_) {
        float s = bgk[c];
        #pragma unroll 8
        for (int i = 0; i < GDIM_; i++) s = fmaf(g[i], Wgk[i * HID_ + c], s);
        float e = (s > 0.f) ? s : (expf(s) - 1.f);
        g_addk[b * HID_ + c] = e + ct_key_emb[ctb * HID_ + c];
    }
}

// ===========================================================================
// tf32 mma.sync GEMM, BK=16, 2 CTAs/SM. blockIdx.z selects {W,bias,C}.
// CTA tile 128x128, 8 warps (wm=w>>2, wn=w&3), warp tile 64x32.
// smem: A[2][8KB] @0, B[2][8KB] @16384. Total 32KB.
// ===========================================================================
#define GEMM_SMEM 32768

__global__ __launch_bounds__(256, 2) void gemm3_mma_kernel(
    const float* __restrict__ A,
    const float* __restrict__ W0, const float* __restrict__ W1,
    const float* __restrict__ W2,
    const float* __restrict__ bi0, const float* __restrict__ bi1,
    const float* __restrict__ bi2,
    const float* __restrict__ addk,
    float* __restrict__ C0, float* __restrict__ C1, float* __restrict__ C2) {
    extern __shared__ float sm[];
    uint32_t Abase = smem_to_u32(sm);
    uint32_t Bbase = Abase + 16384;

    int z = blockIdx.z;
    const float* W = (z == 0) ? W0 : ((z == 1) ? W1 : W2);
    const float* bias = (z == 0) ? bi0 : ((z == 1) ? bi1 : bi2);
    float* C = (z == 0) ? C0 : ((z == 1) ? C1 : C2);
    const float* ak = (z == 1) ? addk : nullptr;

    int tid = threadIdx.x;
    int lane = tid & 31, w = tid >> 5;
    int wm = w >> 2, wn = w & 3;
    int m0 = blockIdx.y * 128, n0 = blockIdx.x * 128;

    int l0 = lane & 1, l1 = (lane >> 1) & 1, l2 = (lane >> 2) & 1;
    int kqA = lane >> 3;                       // 0..3, A quad-column
    int e0A = l2 | (((lane >> 4) & 1) << 1);   // A component stagger
    int a_mbase = w * 16 + l0 + 4 * l2 + 8 * l1;  // + 2*it
    uint32_t a_f = (uint32_t)((kqA >> 1) * 8 + w);
    uint32_t a_reg = (uint32_t)(l1 | ((kqA & 1) << 1));

    int kB = (lane & 7) + 8 * (w & 1);
    int nq_base = (lane >> 3) + 4 * (w >> 1);  // + 16*it
    int e0B = (lane >> 3) & 3;                 // B component stagger

    float c[4][4][4];
    #pragma unroll
    for (int i = 0; i < 4; i++)
        #pragma unroll
        for (int j = 0; j < 4; j++)
            #pragma unroll
            for (int r = 0; r < 4; r++) c[i][j][r] = 0.f;

    float4 aR[2], bR[2];

    #define LDG_CHUNK(k0)                                                      \
        do {                                                                   \
            _Pragma("unroll")                                                  \
            for (int it = 0; it < 2; it++) {                                   \
                int m = a_mbase + 2 * it;                                      \
                aR[it] = *(const float4*)(A + (size_t)(m0 + m) * 1024 +        \
                                          (k0) + kqA * 4);                     \
                int nq = nq_base + 16 * it;                                    \
                bR[it] = *(const float4*)(W + (size_t)((k0) + kB) * 1024 +     \
                                          n0 + nq * 4);                        \
            }                                                                  \
        } while (0)

    #define STS_CHUNK(buf)                                                     \
        do {                                                                   \
            uint32_t Ab = Abase + (buf) * 8192;                                \
            uint32_t Bb = Bbase + (buf) * 8192;                                \
            _Pragma("unroll")                                                  \
            for (int it = 0; it < 2; it++) {                                   \
                int r7 = l0 + 2 * it + 4 * l2;                                 \
                uint32_t base = Ab + a_f * 512 + ((uint32_t)r7 << 6) +         \
                                a_reg * 4;                                     \
                float4 av = rot4(aR[it], e0A);                                 \
                STS32(base + (((e0A + 0) & 3) << 4), f2tf32(av.x));            \
                STS32(base + (((e0A + 1) & 3) << 4), f2tf32(av.y));            \
                STS32(base + (((e0A + 2) & 3) << 4), f2tf32(av.z));            \
                STS32(base + (((e0A + 3) & 3) << 4), f2tf32(av.w));            \
                int nq = nq_base + 16 * it;                                    \
                uint32_t fb = (uint32_t)((w & 1) * 16 + (nq >> 1));            \
                uint32_t baseb = Bb + fb * 256 + (uint32_t)(nq & 1) * 128 +    \
                                 (uint32_t)(kB & 3) * 8 +                      \
                                 (uint32_t)((kB >> 2) & 1) * 4;                \
                float4 bv = rot4(bR[it], e0B);                                 \
                STS32(baseb + (((e0B + 0) & 3) << 5), f2tf32(bv.x));           \
                STS32(baseb + (((e0B + 1) & 3) << 5), f2tf32(bv.y));           \
                STS32(baseb + (((e0B + 2) & 3) << 5), f2tf32(bv.z));           \
                STS32(baseb + (((e0B + 3) & 3) << 5), f2tf32(bv.w));           \
            }                                                                  \
        } while (0)

    LDG_CHUNK(0);
    STS_CHUNK(0);
    __syncthreads();

    for (int ch = 0; ch < 64; ch++) {
        int buf = ch & 1;
        if (ch < 63) LDG_CHUNK((ch + 1) * 16);

        uint32_t Ab = Abase + buf * 8192;
        uint32_t Bb = Bbase + buf * 8192;
        #pragma unroll
        for (int ks = 0; ks < 2; ks++) {
            uint32_t af[4][4], bf[4][2];
            #pragma unroll
            for (int i = 0; i < 4; i++)
                LDS128(Ab + (((uint32_t)(ks * 8 + wm * 4 + i) * 32 + lane) << 4),
                       af[i][0], af[i][1], af[i][2], af[i][3]);
            #pragma unroll
            for (int j = 0; j < 4; j++)
                LDS64(Bb + (((uint32_t)(ks * 16 + wn * 4 + j) * 32 + lane) << 3),
                      bf[j][0], bf[j][1]);
            #pragma unroll
            for (int i = 0; i < 4; i++)
                #pragma unroll
                for (int j = 0; j < 4; j++) mma_tf32(c[i][j], af[i], bf[j]);
        }

        if (ch < 63) STS_CHUNK(buf ^ 1);
        __syncthreads();
    }

    int b = m0 >> 10;
    #pragma unroll
    for (int i = 0; i < 4; i++) {
        int row = m0 + wm * 64 + i * 16 + (lane >> 2);
        #pragma unroll
        for (int j = 0; j < 4; j++) {
            int col = n0 + wn * 32 + j * 8 + (lane & 3) * 2;
            float bb0 = bias[col], bb1 = bias[col + 1];
            if (ak) {
                bb0 += ak[b * HID_ + col];
                bb1 += ak[b * HID_ + col + 1];
            }
            *(float2*)(C + (size_t)row * 1024 + col) =
                make_float2(c[i][j][0] + bb0, c[i][j][1] + bb1);
            *(float2*)(C + (size_t)(row + 8) * 1024 + col) =
                make_float2(c[i][j][2] + bb0, c[i][j][3] + bb1);
        }
    }
}

// ===========================================================================
// Tensor-core flash attention (unchanged from R5)
// ===========================================================================
#define ATTN_SMEM 98816

__global__ __launch_bounds__(256) void attn_mma_kernel(
    const float* __restrict__ Q, const float* __restrict__ K,
    const float* __restrict__ V, const unsigned char* __restrict__ mask,
    float* __restrict__ O) {
    extern __shared__ float sm[];
    uint32_t base = smem_to_u32(sm);
    uint32_t Kf = base;
    uint32_t Vf = base + 32768;
    uint32_t Pw = base + 65536;
    float* Msf = sm + (65536 + 32768) / 4;

    int tid = threadIdx.x;
    int lane = tid & 31, w = tid >> 5;
    int lanehi = lane >> 3;
    int r = lane >> 2, cl = lane & 3;
    int qt = blockIdx.x, h = blockIdx.y, b = blockIdx.z;

    const float* Qg = Q + ((size_t)(b * N_ + qt * 128) * HID_ + h * HD_);
    const float* Kg = K + ((size_t)b * N_ * HID_ + h * HD_);
    const float* Vg = V + ((size_t)b * N_ * HID_ + h * HD_);

    uint32_t qf[8][4];
    #pragma unroll
    for (int ks = 0; ks < 8; ks++)
        #pragma unroll
        for (int reg = 0; reg < 4; reg++) {
            int m = 16 * w + r + 8 * (reg & 1);
            int k = 8 * ks + cl + 4 * (reg >> 1);
            qf[ks][reg] = f2tf32(Qg[(size_t)m * HID_ + k] * 0.125f);
        }

    int kvrow = (lane & 7) + 8 * w;
    float4 kR[4], vR[4];

    #define AT_LDG(t)                                                          \
        do {                                                                   \
            const float* kp = Kg + (size_t)((t) * 64 + kvrow) * HID_;          \
            const float* vp = Vg + (size_t)((t) * 64 + kvrow) * HID_;          \
            _Pragma("unroll")                                                  \
            for (int it = 0; it < 4; it++) {                                   \
                kR[it] = *(const float4*)(kp + (lanehi + 4 * it) * 4);         \
                vR[it] = *(const float4*)(vp + (lanehi + 4 * it) * 4);         \
            }                                                                  \
        } while (0)

    #define AT_STS(buf, t)                                                     \
        do {                                                                   \
            uint32_t Kb = Kf + (buf) * 16384;                                  \
            uint32_t Vb = Vf + (buf) * 16384;                                  \
            int rotK = lanehi >> 1;                                            \
            _Pragma("unroll")                                                  \
            for (int it = 0; it < 4; it++) {                                   \
                int dq = lanehi + 4 * it;                                      \
                uint32_t fragk = (uint32_t)((dq >> 1) * 8 + w);                \
                uint32_t bk = Kb + fragk * 256 + ((uint32_t)(lane & 7) << 5) + \
                              (uint32_t)(dq & 1) * 4;                          \
                float4 kv4 = rot4(kR[it], rotK);                               \
                STS32(bk + (((rotK + 0) & 3) << 3), f2tf32(kv4.x));            \
                STS32(bk + (((rotK + 1) & 3) << 3), f2tf32(kv4.y));            \
                STS32(bk + (((rotK + 2) & 3) << 3), f2tf32(kv4.z));            \
                STS32(bk + (((rotK + 3) & 3) << 3), f2tf32(kv4.w));            \
                uint32_t fragv = (uint32_t)(w * 8 + (dq >> 1));                \
                uint32_t bv = Vb + fragv * 256 +                               \
                              ((uint32_t)(dq & 1) * 4) * 32 +                  \
                              ((uint32_t)(lane & 3)) * 8 +                     \
                              ((uint32_t)((lane >> 2) & 1)) * 4;               \
                float4 vv4 = rot4(vR[it], lanehi);                             \
                uint32_t e0 = (uint32_t)(lanehi & 3);                          \
                STS32(bv + (((e0 + 0) & 3) << 5), f2tf32(vv4.x));              \
                STS32(bv + (((e0 + 1) & 3) << 5), f2tf32(vv4.y));              \
                STS32(bv + (((e0 + 2) & 3) << 5), f2tf32(vv4.z));              \
                STS32(bv + (((e0 + 3) & 3) << 5), f2tf32(vv4.w));              \
            }                                                                  \
            if (tid < 64)                                                      \
                Msf[(buf) * 64 + tid] =                                        \
                    mask[b * N_ + (t) * 64 + tid] ? 0.f : 1.f;                 \
        } while (0)

    float oacc[8][4];
    #pragma unroll
    for (int nf = 0; nf < 8; nf++)
        #pragma unroll
        for (int x = 0; x < 4; x++) oacc[nf][x] = 0.f;
    float sum0 = 0.f, sum1 = 0.f;

    int swz = (r >> 1) & 3;
    uint32_t Pmine = Pw + (uint32_t)w * 4096;
    uint32_t PloadBase = Pmine + (uint32_t)((r << 2) | (cl ^ swz)) * 16;

    AT_LDG(0);
    AT_STS(0, 0);
    __syncthreads();

    for (int t = 0; t < 16; t++) {
        int buf = t & 1;
        if (t < 15) AT_LDG(t + 1);

        uint32_t Kb = Kf + buf * 16384;
        uint32_t Vb = Vf + buf * 16384;

        float sacc[8][4];
        #pragma unroll
        for (int nf = 0; nf < 8; nf++)
            #pragma unroll
            for (int x = 0; x < 4; x++) sacc[nf][x] = 0.f;
        #pragma unroll
        for (int ks = 0; ks < 8; ks++) {
            uint32_t bf[8][2];
            #pragma unroll
            for (int nf = 0; nf < 8; nf++)
                LDS64(Kb + (uint32_t)(ks * 8 + nf) * 256 + (uint32_t)lane * 8,
                      bf[nf][0], bf[nf][1]);
            #pragma unroll
            for (int nf = 0; nf < 8; nf++) mma_tf32(sacc[nf], qf[ks], bf[nf]);
        }

        const float* Mb = Msf + buf * 64;
        #pragma unroll
        for (int nf = 0; nf < 8; nf++) {
            float mm0 = Mb[nf * 8 + 2 * cl];
            float mm1 = Mb[nf * 8 + 2 * cl + 1];
            float p0 = fexp(sacc[nf][0]) * mm0;
            float p1 = fexp(sacc[nf][1]) * mm1;
            float p2 = fexp(sacc[nf][2]) * mm0;
            float p3 = fexp(sacc[nf][3]) * mm1;
            sum0 += p0 + p1;
            sum1 += p2 + p3;
            uint32_t bp = Pmine + (uint32_t)nf * 512 + ((uint32_t)r << 6) +
                          ((uint32_t)(cl >> 1)) * 8;
            uint32_t a_even = bp + (uint32_t)(((2 * (cl & 1)) ^ swz) << 4);
            uint32_t a_odd = bp + (uint32_t)(((2 * (cl & 1) + 1) ^ swz) << 4);
            STS64V(a_even, f2tf32(p0), f2tf32(p2));
            STS64V(a_odd, f2tf32(p1), f2tf32(p3));
        }
        __syncwarp();

        #pragma unroll
        for (int ks = 0; ks < 8; ks++) {
            uint32_t af[4];
            LDS128(PloadBase + (uint32_t)ks * 512, af[0], af[1], af[2], af[3]);
            uint32_t vf2[8][2];
            #pragma unroll
            for (int nf = 0; nf < 8; nf++)
                LDS64(Vb + (uint32_t)(ks * 8 + nf) * 256 + (uint32_t)lane * 8,
                      vf2[nf][0], vf2[nf][1]);
            #pragma unroll
            for (int nf = 0; nf < 8; nf++) mma_tf32(oacc[nf], af, vf2[nf]);
        }
        __syncwarp();

        if (t < 15) {
            __syncthreads();
            AT_STS(buf ^ 1, t + 1);
            __syncthreads();
        }
    }

    sum0 += __shfl_xor_sync(0xffffffffu, sum0, 1);
    sum0 += __shfl_xor_sync(0xffffffffu, sum0, 2);
    sum1 += __shfl_xor_sync(0xffffffffu, sum1, 1);
    sum1 += __shfl_xor_sync(0xffffffffu, sum1, 2);
    float inv0 = 1.f / sum0, inv1 = 1.f / sum1;

    int row0 = b * N_ + qt * 128 + 16 * w + r;
    #pragma unroll
    for (int nf = 0; nf < 8; nf++) {
        int col = h * HD_ + nf * 8 + 2 * cl;
        *(float2*)(O + (size_t)row0 * HID_ + col) =
            make_float2(oacc[nf][0] * inv0, oacc[nf][1] * inv0);
        *(float2*)(O + (size_t)(row0 + 8) * HID_ + col) =
            make_float2(oacc[nf][2] * inv1, oacc[nf][3] * inv1);
    }
}

// ===========================================================================
extern "C" void kernel_launch(void* const* d_in, const int* in_sizes, int n_in,
                              void* d_out, int out_size) {
    const float* x = (const float*)d_in[0];
    const int* ct = (const int*)d_in[1];
    const float* gc = (const float*)d_in[2];
    const unsigned char* mask = (const unsigned char*)d_in[3];
    const float* Wq = (const float*)d_in[4];
    const float* bq = (const float*)d_in[5];
    const float* Wk = (const float*)d_in[6];
    const float* bk = (const float*)d_in[7];
    const float* Wv = (const float*)d_in[8];
    const float* bv = (const float*)d_in[9];
    const float* Wo = (const float*)d_in[10];
    const float* bo = (const float*)d_in[11];
    // d_in[12] ct_bias_emb, d_in[14..17] Wg1/bg1/Wg2/bg2 cancel in softmax
    const float* ct_key = (const float*)d_in[13];
    const float* Wgk = (const float*)d_in[18];
    const float* bgk = (const float*)d_in[19];

    float *Qb, *Kb, *Vb, *Ob, *addk;
    cudaGetSymbolAddress((void**)&Qb, g_Q);
    cudaGetSymbolAddress((void**)&Kb, g_K);
    cudaGetSymbolAddress((void**)&Vb, g_V);
    cudaGetSymbolAddress((void**)&Ob, g_O);
    cudaGetSymbolAddress((void**)&addk, g_addk);

    cudaFuncSetAttribute(gemm3_mma_kernel, cudaFuncAttributeMaxDynamicSharedMemorySize,
                         GEMM_SMEM);
    cudaFuncSetAttribute(attn_mma_kernel, cudaFuncAttributeMaxDynamicSharedMemorySize,
                         ATTN_SMEM);

    prep_addk_kernel<<<B_, GDIM_>>>(ct, gc, Wgk, bgk, ct_key);

    // Fused Q/K/V projections: z selects weight/bias/output; addk applies to K.
    dim3 qkvgrid(HID_ / 128, (B_ * N_) / 128, 3);  // (8, 64, 3)
    gemm3_mma_kernel<<<qkvgrid, 256, GEMM_SMEM>>>(
        x, Wq, Wk, Wv, bq, bk, bv, addk, Qb, Kb, Vb);

    dim3 agrid(N_ / 128, HEADS_, B_);  // (8, 16, 8)
    attn_mma_kernel<<<agrid, 256, ATTN_SMEM>>>(Qb, Kb, Vb, mask, Ob);

    dim3 ogrid(HID_ / 128, (B_ * N_) / 128, 1);
    gemm3_mma_kernel<<<ogrid, 256, GEMM_SMEM>>>(
        Ob, Wo, Wo, Wo, bo, bo, bo, nullptr, (float*)d_out, nullptr, nullptr);
}